// round 13
// baseline (speedup 1.0000x reference)
#include <cuda_runtime.h>
#include <cuda_bf16.h>
#include <math.h>
#include <stdint.h>

// Problem constants
#define Bsz 8
#define Nseq 2048
#define Cdim 768
#define Hn 12
#define Dh 64
#define Mlm 32
#define BH (Bsz*Hn)            // 96
#define KS 1536                // split storage width ([hi|lo])
#define QK_SCALE 0.35355339059327373f  // 64^-0.25

// ---------------- scratch (device globals; no runtime alloc allowed) -------
__device__ float g_qkv[(size_t)3 * BH * Nseq * Dh];         // [3][96][2048][64]
__device__ float g_lm[(size_t)2 * BH * Mlm * Dh];           // Q_l then K_l
__device__ float g_inv[(size_t)BH * Mlm * Mlm];             // pinv(kernel_2)
__device__ float g_F[(size_t)BH * Mlm * Dh];                // kernel_3 @ V
__device__ float g_Fpart[(size_t)BH * 8 * Mlm * 66];        // partial flash outputs
__device__ __nv_bfloat16 g_Acat[(size_t)16384 * KS];        // [Ah|Al] of x
__device__ __nv_bfloat16 g_Xcat[(size_t)16384 * KS];        // [Xh|Xl] of attention out
__device__ __nv_bfloat16 g_Bq[(size_t)2304 * KS];           // w_qkv^T split [N=2304][Bh|Bl]
__device__ __nv_bfloat16 g_Bp[(size_t)Cdim * KS];           // w_proj^T split [N=768][Bh|Bl]

// ============================================================================
// PTX helpers (baseline ISA only: cp.async / ldmatrix / mma.sync)
// ============================================================================
__device__ __forceinline__ uint32_t smem_u32(const void* p) {
    uint32_t a;
    asm("{ .reg .u64 t; cvta.to.shared.u64 t, %1; cvt.u32.u64 %0, t; }" : "=r"(a) : "l"(p));
    return a;
}
#define CP16(dst, src) \
    asm volatile("cp.async.cg.shared.global [%0], [%1], 16;" :: "r"(dst), "l"(src))
#define CP_COMMIT() asm volatile("cp.async.commit_group;" ::: "memory")
#define CP_WAIT0()  asm volatile("cp.async.wait_group 0;" ::: "memory")

__device__ __forceinline__ void ldsm_x4(uint32_t& r0, uint32_t& r1, uint32_t& r2, uint32_t& r3, uint32_t addr) {
    asm volatile("ldmatrix.sync.aligned.m8n8.x4.shared.b16 {%0,%1,%2,%3}, [%4];"
                 : "=r"(r0), "=r"(r1), "=r"(r2), "=r"(r3) : "r"(addr));
}
__device__ __forceinline__ void mma16816(float* d, const uint32_t* a, const uint32_t* b) {
    asm("mma.sync.aligned.m16n8k16.row.col.f32.bf16.bf16.f32 "
        "{%0,%1,%2,%3}, {%4,%5,%6,%7}, {%8,%9}, {%0,%1,%2,%3};"
        : "+f"(d[0]), "+f"(d[1]), "+f"(d[2]), "+f"(d[3])
        : "r"(a[0]), "r"(a[1]), "r"(a[2]), "r"(a[3]), "r"(b[0]), "r"(b[1]));
}

// ============================================================================
// conv_a: x [16384][768] f32 -> g_Acat [16384][1536] bf16  ([Ah|Al])
// ============================================================================
__global__ __launch_bounds__(256) void conv_a(const float* __restrict__ X)
{
    int idx = blockIdx.x * 256 + threadIdx.x;   // 16384*192 total
    int r = idx / 192, c = (idx - r * 192) * 4;
    float4 v = *(const float4*)(X + (size_t)r * Cdim + c);
    float f[4] = {v.x, v.y, v.z, v.w};
    __nv_bfloat16 hi[4], lo[4];
#pragma unroll
    for (int i = 0; i < 4; i++) {
        hi[i] = __float2bfloat16(f[i]);
        lo[i] = __float2bfloat16(f[i] - __bfloat162float(hi[i]));
    }
    __nv_bfloat16* row = g_Acat + (size_t)r * KS;
    __nv_bfloat162 h0 = {hi[0], hi[1]}, h1 = {hi[2], hi[3]};
    __nv_bfloat162 l0 = {lo[0], lo[1]}, l1 = {lo[2], lo[3]};
    *(__nv_bfloat162*)(row + c) = h0;        *(__nv_bfloat162*)(row + c + 2) = h1;
    *(__nv_bfloat162*)(row + 768 + c) = l0;  *(__nv_bfloat162*)(row + 768 + c + 2) = l1;
}

// ============================================================================
// conv_w: W [768][Nw] f32 -> Bt [Nw][1536] bf16 transposed split [Bh|Bl]
// ============================================================================
__global__ __launch_bounds__(256) void conv_w(const float* __restrict__ W,
                                              __nv_bfloat16* __restrict__ Bt, int Nw)
{
    __shared__ float tile[32][33];
    int n0 = blockIdx.x * 32, k0 = blockIdx.y * 32;
    for (int i = threadIdx.y; i < 32; i += 8)
        tile[i][threadIdx.x] = W[(size_t)(k0 + i) * Nw + n0 + threadIdx.x];
    __syncthreads();
    for (int i = threadIdx.y; i < 32; i += 8) {
        int n = n0 + i, k = k0 + threadIdx.x;
        float v = tile[threadIdx.x][i];
        __nv_bfloat16 hi = __float2bfloat16(v);
        __nv_bfloat16 lo = __float2bfloat16(v - __bfloat162float(hi));
        __nv_bfloat16* row = Bt + (size_t)n * KS;
        row[k] = hi;
        row[768 + k] = lo;
    }
}

// ============================================================================
// HMMA bf16 split GEMM with operand sharing:
//   D = Ah*Bh + Ah*Bl + Al*Bh,  24 iterations of BK=32
// 256 threads = 8 warps (2x4), warp tile 64x32. Double-buffered cp.async.
// EPI 0: scatter into g_qkv with QK scale + FUSED landmark pooling -> g_lm.
// EPI 1: +bias -> out.
// ============================================================================
#define SROW 40                        // smem row stride in bf16 (80B, conflict-free)
#define MATB (128 * SROW * 2)          // bytes per 128x32 matrix = 10240
#define STAGE_BYTES (4 * MATB)         // Ah,Bh,Al,Bl = 40960
#define GEMM_SMEM (2 * STAGE_BYTES)    // 81920

template<int EPI>
__global__ __launch_bounds__(256)
void hmma_gemm(const float* __restrict__ bias, float* __restrict__ out)
{
    extern __shared__ __align__(16) char dsm[];
    const uint32_t smem0 = smem_u32(dsm);

    const int tid = threadIdx.x;
    const int warp = tid >> 5, lane = tid & 31;
    const int wm = warp & 1, wn = warp >> 1;   // 2 x 4 warp grid

    const __nv_bfloat16* Ag = (EPI == 0) ? g_Acat : g_Xcat;
    const __nv_bfloat16* Bg = (EPI == 0) ? g_Bq : g_Bp;

    // loader mapping: row = tid>>1, 16 elements at (tid&1)*16 (2 x 16B chunks)
    const int lrow = tid >> 1;
    const int lcolE = (tid & 1) * 16;
    const __nv_bfloat16* Agp = Ag + (size_t)(blockIdx.y * 128 + lrow) * KS + lcolE;
    const __nv_bfloat16* Bgp = Bg + (size_t)(blockIdx.x * 128 + lrow) * KS + lcolE;
    const uint32_t st_off = ((uint32_t)lrow * SROW + lcolE) * 2;

    float acc[4][4][4];
#pragma unroll
    for (int i = 0; i < 4; i++)
#pragma unroll
        for (int j = 0; j < 4; j++)
#pragma unroll
            for (int k = 0; k < 4; k++) acc[i][j][k] = 0.f;

    // ldmatrix per-thread offsets (within one MATB matrix)
    const int l15 = lane & 15;
    const uint32_t a_off = ((uint32_t)(wm * 64 + l15) * SROW + (lane >> 4) * 8) * 2;
    const uint32_t b_off = ((uint32_t)(wn * 32 + ((lane >> 4) & 1) * 8 + (lane & 7)) * SROW
                           + ((lane >> 3) & 1) * 8) * 2;

    const int NIT = 24;   // k = it*32

    // prologue: stage 0  (Ah, Bh at +0/+MATB; Al, Bl at +2*MATB/+3*MATB)
    {
        const uint32_t sa = smem0;
        CP16(sa + 0 * MATB + st_off,      Agp + 0);
        CP16(sa + 0 * MATB + st_off + 16, Agp + 8);
        CP16(sa + 1 * MATB + st_off,      Bgp + 0);
        CP16(sa + 1 * MATB + st_off + 16, Bgp + 8);
        CP16(sa + 2 * MATB + st_off,      Agp + 768);
        CP16(sa + 2 * MATB + st_off + 16, Agp + 768 + 8);
        CP16(sa + 3 * MATB + st_off,      Bgp + 768);
        CP16(sa + 3 * MATB + st_off + 16, Bgp + 768 + 8);
        CP_COMMIT();
    }

    for (int it = 0; it < NIT; ++it) {
        CP_WAIT0();           // stage `it` resident
        __syncthreads();      // all warps done computing stage it-1 (same alt buffer)

        if (it + 1 < NIT) {   // refill other buffer with stage it+1
            const uint32_t sa = smem0 + ((it + 1) & 1) * STAGE_BYTES;
            const int k0 = (it + 1) * 32;
            CP16(sa + 0 * MATB + st_off,      Agp + k0);
            CP16(sa + 0 * MATB + st_off + 16, Agp + k0 + 8);
            CP16(sa + 1 * MATB + st_off,      Bgp + k0);
            CP16(sa + 1 * MATB + st_off + 16, Bgp + k0 + 8);
            CP16(sa + 2 * MATB + st_off,      Agp + 768 + k0);
            CP16(sa + 2 * MATB + st_off + 16, Agp + 768 + k0 + 8);
            CP16(sa + 3 * MATB + st_off,      Bgp + 768 + k0);
            CP16(sa + 3 * MATB + st_off + 16, Bgp + 768 + k0 + 8);
        }
        CP_COMMIT();          // empty commits keep group count semantics

        const uint32_t sbase = smem0 + (it & 1) * STAGE_BYTES;
        const uint32_t aHb = sbase + 0 * MATB;
        const uint32_t bHb = sbase + 1 * MATB;
        const uint32_t aLb = sbase + 2 * MATB;
        const uint32_t bLb = sbase + 3 * MATB;

#pragma unroll
        for (int ks = 0; ks < 2; ks++) {
            const uint32_t kso = (uint32_t)(ks * 16) * 2;
            uint32_t bh[4][2], bl[4][2];
#pragma unroll
            for (int nb = 0; nb < 2; nb++) {
                ldsm_x4(bh[2 * nb][0], bh[2 * nb][1], bh[2 * nb + 1][0], bh[2 * nb + 1][1],
                        bHb + b_off + (uint32_t)(nb * 16 * SROW) * 2 + kso);
                ldsm_x4(bl[2 * nb][0], bl[2 * nb][1], bl[2 * nb + 1][0], bl[2 * nb + 1][1],
                        bLb + b_off + (uint32_t)(nb * 16 * SROW) * 2 + kso);
            }
#pragma unroll
            for (int ma = 0; ma < 4; ma++) {
                uint32_t ah[4], al[4];
                ldsm_x4(ah[0], ah[1], ah[2], ah[3],
                        aHb + a_off + (uint32_t)(ma * 16 * SROW) * 2 + kso);
                ldsm_x4(al[0], al[1], al[2], al[3],
                        aLb + a_off + (uint32_t)(ma * 16 * SROW) * 2 + kso);
#pragma unroll
                for (int na = 0; na < 4; na++) mma16816(acc[ma][na], ah, bh[na]);
#pragma unroll
                for (int na = 0; na < 4; na++) mma16816(acc[ma][na], ah, bl[na]);
#pragma unroll
                for (int na = 0; na < 4; na++) mma16816(acc[ma][na], al, bh[na]);
            }
        }
    }

    // ---------------- epilogue ----------------
#pragma unroll
    for (int ma = 0; ma < 4; ma++) {
        const int r0 = blockIdx.y * 128 + wm * 64 + ma * 16 + (lane >> 2);
#pragma unroll
        for (int na = 0; na < 4; na++) {
            const int c = blockIdx.x * 128 + wn * 32 + na * 8 + (lane & 3) * 2;
            if (EPI == 0) {
                const int which = c / 768;
                const int rem = c - which * 768;
                const int h = rem >> 6;
                const int dd = rem & 63;
                const float sc = (which < 2) ? QK_SCALE : 1.0f;
#pragma unroll
                for (int half = 0; half < 2; half++) {
                    const int r = r0 + half * 8;
                    const int b = r >> 11;
                    const int n = r & 2047;
                    float2 v;
                    v.x = acc[ma][na][2 * half + 0] * sc;
                    v.y = acc[ma][na][2 * half + 1] * sc;
                    *(float2*)(g_qkv + (((size_t)which * BH + b * Hn + h) * Nseq + n) * Dh + dd) = v;
                }
            } else {
                const float bx_ = bias[c], by_ = bias[c + 1];
#pragma unroll
                for (int half = 0; half < 2; half++) {
                    const int r = r0 + half * 8;
                    float2 v;
                    v.x = acc[ma][na][2 * half + 0] + bx_;
                    v.y = acc[ma][na][2 * half + 1] + by_;
                    *(float2*)(out + (size_t)r * Cdim + c) = v;
                }
            }
        }
    }

    // -------- fused landmark pooling (qkv epilogue only, Q and K tiles) -----
    if (EPI == 0) {
        const int which_t = (blockIdx.x * 128) / 768;
        if (which_t < 2) {
            const int b = (blockIdx.y * 128) >> 11;
            // 64-row pool chunk index: tile covers 128 tokens = 2 chunks; wm picks one
            const int i = (((blockIdx.y * 128) & 2047) >> 6) + wm;
#pragma unroll
            for (int na = 0; na < 4; na++) {
#pragma unroll
                for (int j = 0; j < 2; j++) {
                    float v = 0.f;
#pragma unroll
                    for (int ma = 0; ma < 4; ma++)
                        v += acc[ma][na][j] + acc[ma][na][2 + j];
                    v += __shfl_down_sync(~0u, v, 16);
                    v += __shfl_down_sync(~0u, v, 8);
                    v += __shfl_down_sync(~0u, v, 4);
                    if ((lane >> 2) == 0) {
                        const int c = blockIdx.x * 128 + wn * 32 + na * 8 + (lane & 3) * 2 + j;
                        const int rem = c - which_t * 768;
                        const int h = rem >> 6, dd = rem & 63;
                        g_lm[(((size_t)which_t * BH + b * Hn + h) * Mlm + i) * Dh + dd] =
                            v * (QK_SCALE / 64.0f);
                    }
                }
            }
        }
    }
}

// ============================================================================
// kernel_2 = softmax(Q_l K_l^T) + Newton-Schulz pseudo-inverse (6 iters)
// ============================================================================
__global__ __launch_bounds__(1024)
void newton_kernel()
{
    int bh = blockIdx.x;
    int j = threadIdx.x, i = threadIdx.y;
    __shared__ float Ql[32][65], Kl[32][65];
    __shared__ float Km[32][33], Vm[32][33], KV[32][33], Tm[32][33];
    __shared__ float red[1];

    int t = i * 32 + j;
    for (int e = t; e < Mlm * Dh; e += 1024) {
        Ql[e >> 6][e & 63] = g_lm[(size_t)bh * (Mlm * Dh) + e];
        Kl[e >> 6][e & 63] = g_lm[(size_t)(BH + bh) * (Mlm * Dh) + e];
    }
    __syncthreads();

    float s = 0.f;
#pragma unroll
    for (int dd = 0; dd < 64; dd++) s += Ql[i][dd] * Kl[j][dd];
    float mx = s;
    for (int o = 16; o; o >>= 1) mx = fmaxf(mx, __shfl_xor_sync(~0u, mx, o));
    float p = expf(s - mx);
    float sm = p;
    for (int o = 16; o; o >>= 1) sm += __shfl_xor_sync(~0u, sm, o);
    p /= sm;
    Km[i][j] = p;
    __syncthreads();

    if (i == 0) {
        float cs = 0.f;
        for (int r = 0; r < 32; r++) cs += Km[r][j];
        float m2 = cs;
        for (int o = 16; o; o >>= 1) m2 = fmaxf(m2, __shfl_xor_sync(~0u, m2, o));
        if (j == 0) red[0] = m2;
    }
    __syncthreads();
    float denom = red[0];
    Vm[i][j] = Km[j][i] / denom;
    __syncthreads();

    for (int it = 0; it < 6; it++) {
        float kv = 0.f;
#pragma unroll
        for (int k = 0; k < 32; k++) kv += Km[i][k] * Vm[k][j];
        KV[i][j] = kv;
        __syncthreads();
        Tm[i][j] = (i == j ? 7.0f : 0.0f) - kv;
        __syncthreads();
        float u = 0.f;
#pragma unroll
        for (int k = 0; k < 32; k++) u += KV[i][k] * Tm[k][j];
        __syncthreads();
        Tm[i][j] = (i == j ? 15.0f : 0.0f) - u;
        __syncthreads();
        u = 0.f;
#pragma unroll
        for (int k = 0; k < 32; k++) u += KV[i][k] * Tm[k][j];
        __syncthreads();
        Tm[i][j] = (i == j ? 13.0f : 0.0f) - u;
        __syncthreads();
        u = 0.f;
#pragma unroll
        for (int k = 0; k < 32; k++) u += Vm[i][k] * Tm[k][j];
        u *= 0.25f;
        __syncthreads();
        Vm[i][j] = u;
        __syncthreads();
    }
    g_inv[((size_t)bh * 32 + i) * 32 + j] = Vm[i][j];
}

// ============================================================================
// flash_k3_part: partial softmax(Q_l K^T) @ V over a 256-token chunk
// grid (96, 8), 512 threads: 16 warps x 2 landmark rows. 64-token tiles
// (each lane scores tokens l and l+32) -> half the syncs of 32-token tiles.
// ============================================================================
__global__ __launch_bounds__(512)
void flash_k3_part()
{
    int bh = blockIdx.x;
    int chunk = blockIdx.y;
    int tid = threadIdx.x;
    int w = tid >> 5, l = tid & 31;
    __shared__ float Ql[32][65];
    __shared__ float Ks[64][65], Vs[64][65];
    __shared__ float Ps[32][65];

    const float* Kg = g_qkv + ((size_t)1 * BH + bh) * Nseq * Dh;
    const float* Vg = g_qkv + ((size_t)2 * BH + bh) * Nseq * Dh;

    for (int e = tid; e < Mlm * Dh; e += 512)
        Ql[e >> 6][e & 63] = g_lm[(size_t)bh * (Mlm * Dh) + e];

    const int r0 = w * 2, r1 = r0 + 1;
    float m0 = -1e30f, l0 = 0.f, o00 = 0.f, o01 = 0.f;
    float m1 = -1e30f, l1 = 0.f, o10 = 0.f, o11 = 0.f;

    const int tbeg = chunk * 256;
    for (int t0 = tbeg; t0 < tbeg + 256; t0 += 64) {
        __syncthreads();
        for (int e = tid; e < 64 * Dh; e += 512) {
            int rr = e >> 6, c = e & 63;
            Ks[rr][c] = Kg[(size_t)(t0 + rr) * Dh + c];
            Vs[rr][c] = Vg[(size_t)(t0 + rr) * Dh + c];
        }
        __syncthreads();
        // ---- row r0 ----
        {
            float sA = 0.f, sB = 0.f;
#pragma unroll
            for (int dd = 0; dd < 64; dd++) {
                float q = Ql[r0][dd];
                sA += q * Ks[l][dd];
                sB += q * Ks[l + 32][dd];
            }
            float tm = fmaxf(sA, sB);
            for (int o = 16; o; o >>= 1) tm = fmaxf(tm, __shfl_xor_sync(~0u, tm, o));
            float nm = fmaxf(m0, tm);
            float alpha = expf(m0 - nm);
            float pA = expf(sA - nm), pB = expf(sB - nm);
            float ps = pA + pB;
            for (int o = 16; o; o >>= 1) ps += __shfl_xor_sync(~0u, ps, o);
            l0 = l0 * alpha + ps;
            o00 *= alpha; o01 *= alpha;
            Ps[r0][l] = pA; Ps[r0][l + 32] = pB;
            __syncwarp();
#pragma unroll
            for (int k = 0; k < 64; k++) {
                float pk = Ps[r0][k];
                o00 += pk * Vs[k][2 * l];
                o01 += pk * Vs[k][2 * l + 1];
            }
            m0 = nm;
        }
        // ---- row r1 ----
        {
            float sA = 0.f, sB = 0.f;
#pragma unroll
            for (int dd = 0; dd < 64; dd++) {
                float q = Ql[r1][dd];
                sA += q * Ks[l][dd];
                sB += q * Ks[l + 32][dd];
            }
            float tm = fmaxf(sA, sB);
            for (int o = 16; o; o >>= 1) tm = fmaxf(tm, __shfl_xor_sync(~0u, tm, o));
            float nm = fmaxf(m1, tm);
            float alpha = expf(m1 - nm);
            float pA = expf(sA - nm), pB = expf(sB - nm);
            float ps = pA + pB;
            for (int o = 16; o; o >>= 1) ps += __shfl_xor_sync(~0u, ps, o);
            l1 = l1 * alpha + ps;
            o10 *= alpha; o11 *= alpha;
            Ps[r1][l] = pA; Ps[r1][l + 32] = pB;
            __syncwarp();
#pragma unroll
            for (int k = 0; k < 64; k++) {
                float pk = Ps[r1][k];
                o10 += pk * Vs[k][2 * l];
                o11 += pk * Vs[k][2 * l + 1];
            }
            m1 = nm;
        }
    }
    float* P0 = g_Fpart + (((size_t)bh * 8 + chunk) * Mlm + r0) * 66;
    float* P1 = g_Fpart + (((size_t)bh * 8 + chunk) * Mlm + r1) * 66;
    P0[2 * l] = o00; P0[2 * l + 1] = o01;
    P1[2 * l] = o10; P1[2 * l + 1] = o11;
    if (l == 0) { P0[64] = m0; P0[65] = l0; P1[64] = m1; P1[65] = l1; }
}

// combine 8 partials -> g_F  (grid 96, block (64,8))
__global__ __launch_bounds__(512)
void flash_combine()
{
    int bh = blockIdx.x;
    int d = threadIdx.x;
    for (int r = threadIdx.y; r < Mlm; r += 8) {
        const float* base = g_Fpart + (((size_t)bh * 8) * Mlm + r) * 66;
        float mstar = -1e30f;
#pragma unroll
        for (int c = 0; c < 8; c++) mstar = fmaxf(mstar, base[(size_t)c * Mlm * 66 + 64]);
        float L = 0.f, acc = 0.f;
#pragma unroll
        for (int c = 0; c < 8; c++) {
            const float* pc = base + (size_t)c * Mlm * 66;
            float e = expf(pc[64] - mstar);
            L += pc[65] * e;
            acc += pc[d] * e;
        }
        g_F[((size_t)bh * Mlm + r) * Dh + d] = acc / L;
    }
}

// ============================================================================
// X = softmax(Q K_l^T) @ (inv @ F)  -> writes bf16 split rows of g_Xcat
// ============================================================================
__global__ __launch_bounds__(128)
void nys_out()
{
    int bh = blockIdx.y;
    int b = bh / Hn, h = bh - b * Hn;
    int chunk = blockIdx.x;
    int tid = threadIdx.x;

    __shared__ float Kl[32][65];
    __shared__ float Fs[32][65];
    __shared__ float Gs[32][65];
    __shared__ float invs[32][33];

    for (int e = tid; e < Mlm * Dh; e += 128) {
        Kl[e >> 6][e & 63] = g_lm[(size_t)(BH + bh) * (Mlm * Dh) + e];
        Fs[e >> 6][e & 63] = g_F[(size_t)bh * (Mlm * Dh) + e];
    }
    for (int e = tid; e < Mlm * Mlm; e += 128)
        invs[e >> 5][e & 31] = g_inv[(size_t)bh * (Mlm * Mlm) + e];
    __syncthreads();

    for (int e = tid; e < Mlm * Dh; e += 128) {
        int r = e >> 6, c = e & 63;
        float s = 0.f;
#pragma unroll
        for (int k = 0; k < 32; k++) s += invs[r][k] * Fs[k][c];
        Gs[r][c] = s;
    }
    __syncthreads();

    int n = chunk * 128 + tid;
    const float* Qg = g_qkv + ((size_t)bh * Nseq + n) * Dh;
    float q[64];
#pragma unroll
    for (int e = 0; e < 16; e++)
        *(float4*)&q[4 * e] = *(const float4*)&Qg[4 * e];

    float logits[32];
#pragma unroll
    for (int j = 0; j < 32; j++) {
        float s = 0.f;
#pragma unroll
        for (int dd = 0; dd < 64; dd++) s += q[dd] * Kl[j][dd];
        logits[j] = s;
    }
    float mx = -1e30f;
#pragma unroll
    for (int j = 0; j < 32; j++) mx = fmaxf(mx, logits[j]);
    float sum = 0.f;
#pragma unroll
    for (int j = 0; j < 32; j++) { logits[j] = expf(logits[j] - mx); sum += logits[j]; }
    float is = 1.f / sum;
#pragma unroll
    for (int j = 0; j < 32; j++) logits[j] *= is;

    // output row in X_cat: r = b*2048 + n, cols h*64 + dd (split: [Xh|Xl])
    __nv_bfloat16* row = g_Xcat + ((size_t)b * Nseq + n) * KS + h * Dh;
#pragma unroll
    for (int d4 = 0; d4 < 16; d4++) {
        float o[4] = {0.f, 0.f, 0.f, 0.f};
#pragma unroll
        for (int j = 0; j < 32; j++) {
            float pj = logits[j];
            o[0] += pj * Gs[j][4 * d4 + 0];
            o[1] += pj * Gs[j][4 * d4 + 1];
            o[2] += pj * Gs[j][4 * d4 + 2];
            o[3] += pj * Gs[j][4 * d4 + 3];
        }
        __nv_bfloat16 hi[4], lo[4];
#pragma unroll
        for (int i = 0; i < 4; i++) {
            hi[i] = __float2bfloat16(o[i]);
            lo[i] = __float2bfloat16(o[i] - __bfloat162float(hi[i]));
        }
        __nv_bfloat162 h0 = {hi[0], hi[1]}, h1 = {hi[2], hi[3]};
        __nv_bfloat162 l0 = {lo[0], lo[1]}, l1 = {lo[2], lo[3]};
        int c = 4 * d4;
        *(__nv_bfloat162*)(row + c) = h0;        *(__nv_bfloat162*)(row + c + 2) = h1;
        *(__nv_bfloat162*)(row + 768 + c) = l0;  *(__nv_bfloat162*)(row + 768 + c + 2) = l1;
    }
}

// ============================================================================
extern "C" void kernel_launch(void* const* d_in, const int* in_sizes, int n_in,
                              void* d_out, int out_size)
{
    const float* x      = (const float*)d_in[0];  // [8,2048,768]
    const float* w_qkv  = (const float*)d_in[1];  // [768,2304]
    const float* w_proj = (const float*)d_in[2];  // [768,768]
    const float* b_proj = (const float*)d_in[3];  // [768]
    float* out = (float*)d_out;                   // [8,2048,768]

    __nv_bfloat16 *gBq, *gBp;
    cudaGetSymbolAddress((void**)&gBq, g_Bq);
    cudaGetSymbolAddress((void**)&gBp, g_Bp);

    // allow >48KB dynamic smem for the GEMMs (host-side attribute set; idempotent)
    static int attr_done = 0;
    if (!attr_done) {
        cudaFuncSetAttribute(hmma_gemm<0>, cudaFuncAttributeMaxDynamicSharedMemorySize, GEMM_SMEM);
        cudaFuncSetAttribute(hmma_gemm<1>, cudaFuncAttributeMaxDynamicSharedMemorySize, GEMM_SMEM);
        attr_done = 1;
    }

    // 1. bf16 split conversions
    conv_a<<<16384 * 192 / 256, 256>>>(x);
    conv_w<<<dim3(2304 / 32, Cdim / 32), dim3(32, 8)>>>(w_qkv, gBq, 2304);
    conv_w<<<dim3(Cdim / 32, Cdim / 32), dim3(32, 8)>>>(w_proj, gBp, Cdim);
    // 2. qkv GEMM on HMMA + fused landmark pooling -> g_qkv, g_lm
    hmma_gemm<0><<<dim3(2304 / 128, 16384 / 128), 256, GEMM_SMEM>>>(nullptr, nullptr);
    // 3. kernel_2 + Newton-Schulz inverse
    newton_kernel<<<BH, dim3(32, 32)>>>();
    // 4. F = softmax(Q_l K^T) @ V  (split over 8 chunks + combine)
    flash_k3_part<<<dim3(BH, 8), 512>>>();
    flash_combine<<<BH, dim3(64, 8)>>>();
    // 5. X = softmax(Q K_l^T) @ (inv @ F) -> g_Xcat (bf16 split)
    nys_out<<<dim3(Nseq / 128, BH), 128>>>();
    // 6. proj GEMM on HMMA (M=16384, N=768) + bias -> out
    hmma_gemm<1><<<dim3(Cdim / 128, 16384 / 128), 256, GEMM_SMEM>>>(b_proj, out);
}

// round 14
// speedup vs baseline: 1.0449x; 1.0449x over previous
#include <cuda_runtime.h>
#include <cuda_bf16.h>
#include <math.h>
#include <stdint.h>

// Problem constants
#define Bsz 8
#define Nseq 2048
#define Cdim 768
#define Hn 12
#define Dh 64
#define Mlm 32
#define BH (Bsz*Hn)            // 96
#define KS 1536                // split storage width ([hi|lo])
#define QK_SCALE 0.35355339059327373f  // 64^-0.25

// ---------------- scratch (device globals; no runtime alloc allowed) -------
__device__ float g_qkv[(size_t)3 * BH * Nseq * Dh];         // [3][96][2048][64]
__device__ float g_lm[(size_t)2 * BH * Mlm * Dh];           // Q_l then K_l
__device__ float g_inv[(size_t)BH * Mlm * Mlm];             // pinv(kernel_2)
__device__ float g_F[(size_t)BH * Mlm * Dh];                // kernel_3 @ V
__device__ float g_Fpart[(size_t)BH * 8 * Mlm * 66];        // partial flash outputs
__device__ __nv_bfloat16 g_Acat[(size_t)16384 * KS];        // [Ah|Al] of x
__device__ __nv_bfloat16 g_Xcat[(size_t)16384 * KS];        // [Xh|Xl] of attention out
__device__ __nv_bfloat16 g_Bq[(size_t)2304 * KS];           // w_qkv^T split [N=2304][Bh|Bl]
__device__ __nv_bfloat16 g_Bp[(size_t)Cdim * KS];           // w_proj^T split [N=768][Bh|Bl]

// ============================================================================
// PTX helpers (baseline ISA only: cp.async / ldmatrix / mma.sync)
// ============================================================================
__device__ __forceinline__ uint32_t smem_u32(const void* p) {
    uint32_t a;
    asm("{ .reg .u64 t; cvta.to.shared.u64 t, %1; cvt.u32.u64 %0, t; }" : "=r"(a) : "l"(p));
    return a;
}
#define CP16(dst, src) \
    asm volatile("cp.async.cg.shared.global [%0], [%1], 16;" :: "r"(dst), "l"(src))
#define CP_COMMIT() asm volatile("cp.async.commit_group;" ::: "memory")
#define CP_WAIT0()  asm volatile("cp.async.wait_group 0;" ::: "memory")

__device__ __forceinline__ void ldsm_x4(uint32_t& r0, uint32_t& r1, uint32_t& r2, uint32_t& r3, uint32_t addr) {
    asm volatile("ldmatrix.sync.aligned.m8n8.x4.shared.b16 {%0,%1,%2,%3}, [%4];"
                 : "=r"(r0), "=r"(r1), "=r"(r2), "=r"(r3) : "r"(addr));
}
__device__ __forceinline__ void mma16816(float* d, const uint32_t* a, const uint32_t* b) {
    asm("mma.sync.aligned.m16n8k16.row.col.f32.bf16.bf16.f32 "
        "{%0,%1,%2,%3}, {%4,%5,%6,%7}, {%8,%9}, {%0,%1,%2,%3};"
        : "+f"(d[0]), "+f"(d[1]), "+f"(d[2]), "+f"(d[3])
        : "r"(a[0]), "r"(a[1]), "r"(a[2]), "r"(a[3]), "r"(b[0]), "r"(b[1]));
}

// ============================================================================
// conv_a: x [16384][768] f32 -> g_Acat [16384][1536] bf16  ([Ah|Al])
// ============================================================================
__global__ __launch_bounds__(256) void conv_a(const float* __restrict__ X)
{
    int idx = blockIdx.x * 256 + threadIdx.x;   // 16384*192 total
    int r = idx / 192, c = (idx - r * 192) * 4;
    float4 v = *(const float4*)(X + (size_t)r * Cdim + c);
    float f[4] = {v.x, v.y, v.z, v.w};
    __nv_bfloat16 hi[4], lo[4];
#pragma unroll
    for (int i = 0; i < 4; i++) {
        hi[i] = __float2bfloat16(f[i]);
        lo[i] = __float2bfloat16(f[i] - __bfloat162float(hi[i]));
    }
    __nv_bfloat16* row = g_Acat + (size_t)r * KS;
    __nv_bfloat162 h0 = {hi[0], hi[1]}, h1 = {hi[2], hi[3]};
    __nv_bfloat162 l0 = {lo[0], lo[1]}, l1 = {lo[2], lo[3]};
    *(__nv_bfloat162*)(row + c) = h0;        *(__nv_bfloat162*)(row + c + 2) = h1;
    *(__nv_bfloat162*)(row + 768 + c) = l0;  *(__nv_bfloat162*)(row + 768 + c + 2) = l1;
}

// ============================================================================
// conv_w: W [768][Nw] f32 -> Bt [Nw][1536] bf16 transposed split [Bh|Bl]
// ============================================================================
__global__ __launch_bounds__(256) void conv_w(const float* __restrict__ W,
                                              __nv_bfloat16* __restrict__ Bt, int Nw)
{
    __shared__ float tile[32][33];
    int n0 = blockIdx.x * 32, k0 = blockIdx.y * 32;
    for (int i = threadIdx.y; i < 32; i += 8)
        tile[i][threadIdx.x] = W[(size_t)(k0 + i) * Nw + n0 + threadIdx.x];
    __syncthreads();
    for (int i = threadIdx.y; i < 32; i += 8) {
        int n = n0 + i, k = k0 + threadIdx.x;
        float v = tile[threadIdx.x][i];
        __nv_bfloat16 hi = __float2bfloat16(v);
        __nv_bfloat16 lo = __float2bfloat16(v - __bfloat162float(hi));
        __nv_bfloat16* row = Bt + (size_t)n * KS;
        row[k] = hi;
        row[768 + k] = lo;
    }
}

// ============================================================================
// HMMA bf16 split GEMM with operand sharing:
//   D = Ah*Bh + Ah*Bl + Al*Bh,  24 iterations of BK=32
// 256 threads = 8 warps (2x4), warp tile 64x32. Double-buffered cp.async.
// EPI 0: scatter into g_qkv with QK scale.  EPI 1: +bias -> out.
// (regs must stay at 128 -> 2 CTAs/SM; add NOTHING to this kernel)
// ============================================================================
#define SROW 40                        // smem row stride in bf16 (80B, conflict-free)
#define MATB (128 * SROW * 2)          // bytes per 128x32 matrix = 10240
#define STAGE_BYTES (4 * MATB)         // Ah,Bh,Al,Bl = 40960
#define GEMM_SMEM (2 * STAGE_BYTES)    // 81920

template<int EPI>
__global__ __launch_bounds__(256)
void hmma_gemm(const float* __restrict__ bias, float* __restrict__ out)
{
    extern __shared__ __align__(16) char dsm[];
    const uint32_t smem0 = smem_u32(dsm);

    const int tid = threadIdx.x;
    const int warp = tid >> 5, lane = tid & 31;
    const int wm = warp & 1, wn = warp >> 1;   // 2 x 4 warp grid

    const __nv_bfloat16* Ag = (EPI == 0) ? g_Acat : g_Xcat;
    const __nv_bfloat16* Bg = (EPI == 0) ? g_Bq : g_Bp;

    // loader mapping: row = tid>>1, 16 elements at (tid&1)*16 (2 x 16B chunks)
    const int lrow = tid >> 1;
    const int lcolE = (tid & 1) * 16;
    const __nv_bfloat16* Agp = Ag + (size_t)(blockIdx.y * 128 + lrow) * KS + lcolE;
    const __nv_bfloat16* Bgp = Bg + (size_t)(blockIdx.x * 128 + lrow) * KS + lcolE;
    const uint32_t st_off = ((uint32_t)lrow * SROW + lcolE) * 2;

    float acc[4][4][4];
#pragma unroll
    for (int i = 0; i < 4; i++)
#pragma unroll
        for (int j = 0; j < 4; j++)
#pragma unroll
            for (int k = 0; k < 4; k++) acc[i][j][k] = 0.f;

    // ldmatrix per-thread offsets (within one MATB matrix)
    const int l15 = lane & 15;
    const uint32_t a_off = ((uint32_t)(wm * 64 + l15) * SROW + (lane >> 4) * 8) * 2;
    const uint32_t b_off = ((uint32_t)(wn * 32 + ((lane >> 4) & 1) * 8 + (lane & 7)) * SROW
                           + ((lane >> 3) & 1) * 8) * 2;

    const int NIT = 24;   // k = it*32

    // prologue: stage 0  (Ah, Bh at +0/+MATB; Al, Bl at +2*MATB/+3*MATB)
    {
        const uint32_t sa = smem0;
        CP16(sa + 0 * MATB + st_off,      Agp + 0);
        CP16(sa + 0 * MATB + st_off + 16, Agp + 8);
        CP16(sa + 1 * MATB + st_off,      Bgp + 0);
        CP16(sa + 1 * MATB + st_off + 16, Bgp + 8);
        CP16(sa + 2 * MATB + st_off,      Agp + 768);
        CP16(sa + 2 * MATB + st_off + 16, Agp + 768 + 8);
        CP16(sa + 3 * MATB + st_off,      Bgp + 768);
        CP16(sa + 3 * MATB + st_off + 16, Bgp + 768 + 8);
        CP_COMMIT();
    }

    for (int it = 0; it < NIT; ++it) {
        CP_WAIT0();           // stage `it` resident
        __syncthreads();      // all warps done computing stage it-1 (same alt buffer)

        if (it + 1 < NIT) {   // refill other buffer with stage it+1
            const uint32_t sa = smem0 + ((it + 1) & 1) * STAGE_BYTES;
            const int k0 = (it + 1) * 32;
            CP16(sa + 0 * MATB + st_off,      Agp + k0);
            CP16(sa + 0 * MATB + st_off + 16, Agp + k0 + 8);
            CP16(sa + 1 * MATB + st_off,      Bgp + k0);
            CP16(sa + 1 * MATB + st_off + 16, Bgp + k0 + 8);
            CP16(sa + 2 * MATB + st_off,      Agp + 768 + k0);
            CP16(sa + 2 * MATB + st_off + 16, Agp + 768 + k0 + 8);
            CP16(sa + 3 * MATB + st_off,      Bgp + 768 + k0);
            CP16(sa + 3 * MATB + st_off + 16, Bgp + 768 + k0 + 8);
        }
        CP_COMMIT();          // empty commits keep group count semantics

        const uint32_t sbase = smem0 + (it & 1) * STAGE_BYTES;
        const uint32_t aHb = sbase + 0 * MATB;
        const uint32_t bHb = sbase + 1 * MATB;
        const uint32_t aLb = sbase + 2 * MATB;
        const uint32_t bLb = sbase + 3 * MATB;

#pragma unroll
        for (int ks = 0; ks < 2; ks++) {
            const uint32_t kso = (uint32_t)(ks * 16) * 2;
            uint32_t bh[4][2], bl[4][2];
#pragma unroll
            for (int nb = 0; nb < 2; nb++) {
                ldsm_x4(bh[2 * nb][0], bh[2 * nb][1], bh[2 * nb + 1][0], bh[2 * nb + 1][1],
                        bHb + b_off + (uint32_t)(nb * 16 * SROW) * 2 + kso);
                ldsm_x4(bl[2 * nb][0], bl[2 * nb][1], bl[2 * nb + 1][0], bl[2 * nb + 1][1],
                        bLb + b_off + (uint32_t)(nb * 16 * SROW) * 2 + kso);
            }
#pragma unroll
            for (int ma = 0; ma < 4; ma++) {
                uint32_t ah[4], al[4];
                ldsm_x4(ah[0], ah[1], ah[2], ah[3],
                        aHb + a_off + (uint32_t)(ma * 16 * SROW) * 2 + kso);
                ldsm_x4(al[0], al[1], al[2], al[3],
                        aLb + a_off + (uint32_t)(ma * 16 * SROW) * 2 + kso);
#pragma unroll
                for (int na = 0; na < 4; na++) mma16816(acc[ma][na], ah, bh[na]);
#pragma unroll
                for (int na = 0; na < 4; na++) mma16816(acc[ma][na], ah, bl[na]);
#pragma unroll
                for (int na = 0; na < 4; na++) mma16816(acc[ma][na], al, bh[na]);
            }
        }
    }

    // ---------------- epilogue ----------------
#pragma unroll
    for (int ma = 0; ma < 4; ma++) {
        const int r0 = blockIdx.y * 128 + wm * 64 + ma * 16 + (lane >> 2);
#pragma unroll
        for (int na = 0; na < 4; na++) {
            const int c = blockIdx.x * 128 + wn * 32 + na * 8 + (lane & 3) * 2;
            if (EPI == 0) {
                const int which = c / 768;
                const int rem = c - which * 768;
                const int h = rem >> 6;
                const int dd = rem & 63;
                const float sc = (which < 2) ? QK_SCALE : 1.0f;
#pragma unroll
                for (int half = 0; half < 2; half++) {
                    const int r = r0 + half * 8;
                    const int b = r >> 11;
                    const int n = r & 2047;
                    float2 v;
                    v.x = acc[ma][na][2 * half + 0] * sc;
                    v.y = acc[ma][na][2 * half + 1] * sc;
                    *(float2*)(g_qkv + (((size_t)which * BH + b * Hn + h) * Nseq + n) * Dh + dd) = v;
                }
            } else {
                const float bx_ = bias[c], by_ = bias[c + 1];
#pragma unroll
                for (int half = 0; half < 2; half++) {
                    const int r = r0 + half * 8;
                    float2 v;
                    v.x = acc[ma][na][2 * half + 0] + bx_;
                    v.y = acc[ma][na][2 * half + 1] + by_;
                    *(float2*)(out + (size_t)r * Cdim + c) = v;
                }
            }
        }
    }
}

// ============================================================================
// Landmark pooling: mean over contiguous chunks of 64
// ============================================================================
__global__ void pool_kernel()
{
    int idx = blockIdx.x * 256 + threadIdx.x;
    int dd = idx & 63;
    int i = (idx >> 6) & 31;
    int rest = idx >> 11;            // which*96 + bh  (which in {0,1})
    const float* src = g_qkv + (size_t)rest * Nseq * Dh + (size_t)(i * 64) * Dh + dd;
    float s = 0.f;
#pragma unroll 8
    for (int t = 0; t < 64; t++) s += src[(size_t)t * Dh];
    g_lm[idx] = s * (1.0f / 64.0f);
}

// ============================================================================
// kernel_2 = softmax(Q_l K_l^T) + Newton-Schulz pseudo-inverse (6 iters)
// ============================================================================
__global__ __launch_bounds__(1024)
void newton_kernel()
{
    int bh = blockIdx.x;
    int j = threadIdx.x, i = threadIdx.y;
    __shared__ float Ql[32][65], Kl[32][65];
    __shared__ float Km[32][33], Vm[32][33], KV[32][33], Tm[32][33];
    __shared__ float red[1];

    int t = i * 32 + j;
    for (int e = t; e < Mlm * Dh; e += 1024) {
        Ql[e >> 6][e & 63] = g_lm[(size_t)bh * (Mlm * Dh) + e];
        Kl[e >> 6][e & 63] = g_lm[(size_t)(BH + bh) * (Mlm * Dh) + e];
    }
    __syncthreads();

    float s = 0.f;
#pragma unroll
    for (int dd = 0; dd < 64; dd++) s += Ql[i][dd] * Kl[j][dd];
    float mx = s;
    for (int o = 16; o; o >>= 1) mx = fmaxf(mx, __shfl_xor_sync(~0u, mx, o));
    float p = expf(s - mx);
    float sm = p;
    for (int o = 16; o; o >>= 1) sm += __shfl_xor_sync(~0u, sm, o);
    p /= sm;
    Km[i][j] = p;
    __syncthreads();

    if (i == 0) {
        float cs = 0.f;
        for (int r = 0; r < 32; r++) cs += Km[r][j];
        float m2 = cs;
        for (int o = 16; o; o >>= 1) m2 = fmaxf(m2, __shfl_xor_sync(~0u, m2, o));
        if (j == 0) red[0] = m2;
    }
    __syncthreads();
    float denom = red[0];
    Vm[i][j] = Km[j][i] / denom;
    __syncthreads();

    for (int it = 0; it < 6; it++) {
        float kv = 0.f;
#pragma unroll
        for (int k = 0; k < 32; k++) kv += Km[i][k] * Vm[k][j];
        KV[i][j] = kv;
        __syncthreads();
        Tm[i][j] = (i == j ? 7.0f : 0.0f) - kv;
        __syncthreads();
        float u = 0.f;
#pragma unroll
        for (int k = 0; k < 32; k++) u += KV[i][k] * Tm[k][j];
        __syncthreads();
        Tm[i][j] = (i == j ? 15.0f : 0.0f) - u;
        __syncthreads();
        u = 0.f;
#pragma unroll
        for (int k = 0; k < 32; k++) u += KV[i][k] * Tm[k][j];
        __syncthreads();
        Tm[i][j] = (i == j ? 13.0f : 0.0f) - u;
        __syncthreads();
        u = 0.f;
#pragma unroll
        for (int k = 0; k < 32; k++) u += Vm[i][k] * Tm[k][j];
        u *= 0.25f;
        __syncthreads();
        Vm[i][j] = u;
        __syncthreads();
    }
    g_inv[((size_t)bh * 32 + i) * 32 + j] = Vm[i][j];
}

// ============================================================================
// flash_k3_part: partial softmax(Q_l K^T) @ V over a 256-token chunk
// grid (96, 8), 512 threads: 16 warps x 2 landmark rows. 64-token tiles
// (each lane scores tokens l and l+32) -> half the syncs of 32-token tiles.
// ============================================================================
__global__ __launch_bounds__(512)
void flash_k3_part()
{
    int bh = blockIdx.x;
    int chunk = blockIdx.y;
    int tid = threadIdx.x;
    int w = tid >> 5, l = tid & 31;
    __shared__ float Ql[32][65];
    __shared__ float Ks[64][65], Vs[64][65];
    __shared__ float Ps[32][65];

    const float* Kg = g_qkv + ((size_t)1 * BH + bh) * Nseq * Dh;
    const float* Vg = g_qkv + ((size_t)2 * BH + bh) * Nseq * Dh;

    for (int e = tid; e < Mlm * Dh; e += 512)
        Ql[e >> 6][e & 63] = g_lm[(size_t)bh * (Mlm * Dh) + e];

    const int r0 = w * 2, r1 = r0 + 1;
    float m0 = -1e30f, l0 = 0.f, o00 = 0.f, o01 = 0.f;
    float m1 = -1e30f, l1 = 0.f, o10 = 0.f, o11 = 0.f;

    const int tbeg = chunk * 256;
    for (int t0 = tbeg; t0 < tbeg + 256; t0 += 64) {
        __syncthreads();
        for (int e = tid; e < 64 * Dh; e += 512) {
            int rr = e >> 6, c = e & 63;
            Ks[rr][c] = Kg[(size_t)(t0 + rr) * Dh + c];
            Vs[rr][c] = Vg[(size_t)(t0 + rr) * Dh + c];
        }
        __syncthreads();
        // ---- row r0 ----
        {
            float sA = 0.f, sB = 0.f;
#pragma unroll
            for (int dd = 0; dd < 64; dd++) {
                float q = Ql[r0][dd];
                sA += q * Ks[l][dd];
                sB += q * Ks[l + 32][dd];
            }
            float tm = fmaxf(sA, sB);
            for (int o = 16; o; o >>= 1) tm = fmaxf(tm, __shfl_xor_sync(~0u, tm, o));
            float nm = fmaxf(m0, tm);
            float alpha = expf(m0 - nm);
            float pA = expf(sA - nm), pB = expf(sB - nm);
            float ps = pA + pB;
            for (int o = 16; o; o >>= 1) ps += __shfl_xor_sync(~0u, ps, o);
            l0 = l0 * alpha + ps;
            o00 *= alpha; o01 *= alpha;
            Ps[r0][l] = pA; Ps[r0][l + 32] = pB;
            __syncwarp();
#pragma unroll
            for (int k = 0; k < 64; k++) {
                float pk = Ps[r0][k];
                o00 += pk * Vs[k][2 * l];
                o01 += pk * Vs[k][2 * l + 1];
            }
            m0 = nm;
        }
        // ---- row r1 ----
        {
            float sA = 0.f, sB = 0.f;
#pragma unroll
            for (int dd = 0; dd < 64; dd++) {
                float q = Ql[r1][dd];
                sA += q * Ks[l][dd];
                sB += q * Ks[l + 32][dd];
            }
            float tm = fmaxf(sA, sB);
            for (int o = 16; o; o >>= 1) tm = fmaxf(tm, __shfl_xor_sync(~0u, tm, o));
            float nm = fmaxf(m1, tm);
            float alpha = expf(m1 - nm);
            float pA = expf(sA - nm), pB = expf(sB - nm);
            float ps = pA + pB;
            for (int o = 16; o; o >>= 1) ps += __shfl_xor_sync(~0u, ps, o);
            l1 = l1 * alpha + ps;
            o10 *= alpha; o11 *= alpha;
            Ps[r1][l] = pA; Ps[r1][l + 32] = pB;
            __syncwarp();
#pragma unroll
            for (int k = 0; k < 64; k++) {
                float pk = Ps[r1][k];
                o10 += pk * Vs[k][2 * l];
                o11 += pk * Vs[k][2 * l + 1];
            }
            m1 = nm;
        }
    }
    float* P0 = g_Fpart + (((size_t)bh * 8 + chunk) * Mlm + r0) * 66;
    float* P1 = g_Fpart + (((size_t)bh * 8 + chunk) * Mlm + r1) * 66;
    P0[2 * l] = o00; P0[2 * l + 1] = o01;
    P1[2 * l] = o10; P1[2 * l + 1] = o11;
    if (l == 0) { P0[64] = m0; P0[65] = l0; P1[64] = m1; P1[65] = l1; }
}

// combine 8 partials -> g_F  (grid 96, block (64,8))
__global__ __launch_bounds__(512)
void flash_combine()
{
    int bh = blockIdx.x;
    int d = threadIdx.x;
    for (int r = threadIdx.y; r < Mlm; r += 8) {
        const float* base = g_Fpart + (((size_t)bh * 8) * Mlm + r) * 66;
        float mstar = -1e30f;
#pragma unroll
        for (int c = 0; c < 8; c++) mstar = fmaxf(mstar, base[(size_t)c * Mlm * 66 + 64]);
        float L = 0.f, acc = 0.f;
#pragma unroll
        for (int c = 0; c < 8; c++) {
            const float* pc = base + (size_t)c * Mlm * 66;
            float e = expf(pc[64] - mstar);
            L += pc[65] * e;
            acc += pc[d] * e;
        }
        g_F[((size_t)bh * Mlm + r) * Dh + d] = acc / L;
    }
}

// ============================================================================
// X = softmax(Q K_l^T) @ (inv @ F)  -> writes bf16 split rows of g_Xcat
// ============================================================================
__global__ __launch_bounds__(128)
void nys_out()
{
    int bh = blockIdx.y;
    int b = bh / Hn, h = bh - b * Hn;
    int chunk = blockIdx.x;
    int tid = threadIdx.x;

    __shared__ float Kl[32][65];
    __shared__ float Fs[32][65];
    __shared__ float Gs[32][65];
    __shared__ float invs[32][33];

    for (int e = tid; e < Mlm * Dh; e += 128) {
        Kl[e >> 6][e & 63] = g_lm[(size_t)(BH + bh) * (Mlm * Dh) + e];
        Fs[e >> 6][e & 63] = g_F[(size_t)bh * (Mlm * Dh) + e];
    }
    for (int e = tid; e < Mlm * Mlm; e += 128)
        invs[e >> 5][e & 31] = g_inv[(size_t)bh * (Mlm * Mlm) + e];
    __syncthreads();

    for (int e = tid; e < Mlm * Dh; e += 128) {
        int r = e >> 6, c = e & 63;
        float s = 0.f;
#pragma unroll
        for (int k = 0; k < 32; k++) s += invs[r][k] * Fs[k][c];
        Gs[r][c] = s;
    }
    __syncthreads();

    int n = chunk * 128 + tid;
    const float* Qg = g_qkv + ((size_t)bh * Nseq + n) * Dh;
    float q[64];
#pragma unroll
    for (int e = 0; e < 16; e++)
        *(float4*)&q[4 * e] = *(const float4*)&Qg[4 * e];

    float logits[32];
#pragma unroll
    for (int j = 0; j < 32; j++) {
        float s = 0.f;
#pragma unroll
        for (int dd = 0; dd < 64; dd++) s += q[dd] * Kl[j][dd];
        logits[j] = s;
    }
    float mx = -1e30f;
#pragma unroll
    for (int j = 0; j < 32; j++) mx = fmaxf(mx, logits[j]);
    float sum = 0.f;
#pragma unroll
    for (int j = 0; j < 32; j++) { logits[j] = expf(logits[j] - mx); sum += logits[j]; }
    float is = 1.f / sum;
#pragma unroll
    for (int j = 0; j < 32; j++) logits[j] *= is;

    // output row in X_cat: r = b*2048 + n, cols h*64 + dd (split: [Xh|Xl])
    __nv_bfloat16* row = g_Xcat + ((size_t)b * Nseq + n) * KS + h * Dh;
#pragma unroll
    for (int d4 = 0; d4 < 16; d4++) {
        float o[4] = {0.f, 0.f, 0.f, 0.f};
#pragma unroll
        for (int j = 0; j < 32; j++) {
            float pj = logits[j];
            o[0] += pj * Gs[j][4 * d4 + 0];
            o[1] += pj * Gs[j][4 * d4 + 1];
            o[2] += pj * Gs[j][4 * d4 + 2];
            o[3] += pj * Gs[j][4 * d4 + 3];
        }
        __nv_bfloat16 hi[4], lo[4];
#pragma unroll
        for (int i = 0; i < 4; i++) {
            hi[i] = __float2bfloat16(o[i]);
            lo[i] = __float2bfloat16(o[i] - __bfloat162float(hi[i]));
        }
        __nv_bfloat162 h0 = {hi[0], hi[1]}, h1 = {hi[2], hi[3]};
        __nv_bfloat162 l0 = {lo[0], lo[1]}, l1 = {lo[2], lo[3]};
        int c = 4 * d4;
        *(__nv_bfloat162*)(row + c) = h0;        *(__nv_bfloat162*)(row + c + 2) = h1;
        *(__nv_bfloat162*)(row + 768 + c) = l0;  *(__nv_bfloat162*)(row + 768 + c + 2) = l1;
    }
}

// ============================================================================
extern "C" void kernel_launch(void* const* d_in, const int* in_sizes, int n_in,
                              void* d_out, int out_size)
{
    const float* x      = (const float*)d_in[0];  // [8,2048,768]
    const float* w_qkv  = (const float*)d_in[1];  // [768,2304]
    const float* w_proj = (const float*)d_in[2];  // [768,768]
    const float* b_proj = (const float*)d_in[3];  // [768]
    float* out = (float*)d_out;                   // [8,2048,768]

    __nv_bfloat16 *gBq, *gBp;
    cudaGetSymbolAddress((void**)&gBq, g_Bq);
    cudaGetSymbolAddress((void**)&gBp, g_Bp);

    // allow >48KB dynamic smem for the GEMMs (host-side attribute set; idempotent)
    static int attr_done = 0;
    if (!attr_done) {
        cudaFuncSetAttribute(hmma_gemm<0>, cudaFuncAttributeMaxDynamicSharedMemorySize, GEMM_SMEM);
        cudaFuncSetAttribute(hmma_gemm<1>, cudaFuncAttributeMaxDynamicSharedMemorySize, GEMM_SMEM);
        attr_done = 1;
    }

    // 1. bf16 split conversions
    conv_a<<<16384 * 192 / 256, 256>>>(x);
    conv_w<<<dim3(2304 / 32, Cdim / 32), dim3(32, 8)>>>(w_qkv, gBq, 2304);
    conv_w<<<dim3(Cdim / 32, Cdim / 32), dim3(32, 8)>>>(w_proj, gBp, Cdim);
    // 2. qkv GEMM on HMMA (M=16384, N=2304, shared-operand 3-product split)
    hmma_gemm<0><<<dim3(2304 / 128, 16384 / 128), 256, GEMM_SMEM>>>(nullptr, nullptr);
    // 3. landmark pooling
    pool_kernel<<<2 * BH * Mlm * Dh / 256, 256>>>();
    // 4. kernel_2 + Newton-Schulz inverse
    newton_kernel<<<BH, dim3(32, 32)>>>();
    // 5. F = softmax(Q_l K^T) @ V  (split over 8 chunks + combine)
    flash_k3_part<<<dim3(BH, 8), 512>>>();
    flash_combine<<<BH, dim3(64, 8)>>>();
    // 6. X = softmax(Q K_l^T) @ (inv @ F) -> g_Xcat (bf16 split)
    nys_out<<<dim3(Nseq / 128, BH), 128>>>();
    // 7. proj GEMM on HMMA (M=16384, N=768) + bias -> out
    hmma_gemm<1><<<dim3(Cdim / 128, 16384 / 128), 256, GEMM_SMEM>>>(b_proj, out);
}

// round 15
// speedup vs baseline: 1.6613x; 1.5900x over previous
#include <cuda_runtime.h>
#include <cuda_bf16.h>
#include <cuda_fp16.h>
#include <math.h>
#include <stdint.h>

// Problem constants
#define Bsz 8
#define Nseq 2048
#define Cdim 768
#define Hn 12
#define Dh 64
#define Mlm 32
#define BH (Bsz*Hn)            // 96
#define QK_SCALE 0.35355339059327373f  // 64^-0.25

// ---------------- scratch (device globals; no runtime alloc allowed) -------
__device__ float g_qkv[(size_t)3 * BH * Nseq * Dh];         // [3][96][2048][64]
__device__ float g_lm[(size_t)2 * BH * Mlm * Dh];           // Q_l then K_l
__device__ float g_inv[(size_t)BH * Mlm * Mlm];             // pinv(kernel_2)
__device__ float g_F[(size_t)BH * Mlm * Dh];                // kernel_3 @ V
__device__ float g_Fpart[(size_t)BH * 8 * Mlm * 66];        // partial flash outputs
__device__ __half g_Ah[(size_t)16384 * Cdim];               // fp16 of x
__device__ __half g_Xh[(size_t)16384 * Cdim];               // fp16 of attention out
__device__ __half g_Bq[(size_t)2304 * Cdim];                // w_qkv^T fp16 [2304][768]
__device__ __half g_Bp[(size_t)Cdim * Cdim];                // w_proj^T fp16 [768][768]

// ============================================================================
// PTX helpers (baseline ISA only: cp.async / ldmatrix / mma.sync)
// ============================================================================
__device__ __forceinline__ uint32_t smem_u32(const void* p) {
    uint32_t a;
    asm("{ .reg .u64 t; cvta.to.shared.u64 t, %1; cvt.u32.u64 %0, t; }" : "=r"(a) : "l"(p));
    return a;
}
#define CP16(dst, src) \
    asm volatile("cp.async.cg.shared.global [%0], [%1], 16;" :: "r"(dst), "l"(src))
#define CP_COMMIT() asm volatile("cp.async.commit_group;" ::: "memory")
#define CP_WAIT0()  asm volatile("cp.async.wait_group 0;" ::: "memory")

__device__ __forceinline__ void ldsm_x4(uint32_t& r0, uint32_t& r1, uint32_t& r2, uint32_t& r3, uint32_t addr) {
    asm volatile("ldmatrix.sync.aligned.m8n8.x4.shared.b16 {%0,%1,%2,%3}, [%4];"
                 : "=r"(r0), "=r"(r1), "=r"(r2), "=r"(r3) : "r"(addr));
}
__device__ __forceinline__ void mma16816(float* d, const uint32_t* a, const uint32_t* b) {
    asm("mma.sync.aligned.m16n8k16.row.col.f32.f16.f16.f32 "
        "{%0,%1,%2,%3}, {%4,%5,%6,%7}, {%8,%9}, {%0,%1,%2,%3};"
        : "+f"(d[0]), "+f"(d[1]), "+f"(d[2]), "+f"(d[3])
        : "r"(a[0]), "r"(a[1]), "r"(a[2]), "r"(a[3]), "r"(b[0]), "r"(b[1]));
}

// ============================================================================
// conv_a: x [16384][768] f32 -> g_Ah [16384][768] fp16
// ============================================================================
__global__ __launch_bounds__(256) void conv_a(const float* __restrict__ X)
{
    int idx = blockIdx.x * 256 + threadIdx.x;   // 16384*192 total
    int r = idx / 192, c = (idx - r * 192) * 4;
    float4 v = *(const float4*)(X + (size_t)r * Cdim + c);
    __half2 h0 = {__float2half(v.x), __float2half(v.y)};
    __half2 h1 = {__float2half(v.z), __float2half(v.w)};
    __half* row = g_Ah + (size_t)r * Cdim;
    *(__half2*)(row + c) = h0;
    *(__half2*)(row + c + 2) = h1;
}

// ============================================================================
// conv_w: W [768][Nw] f32 -> Bt [Nw][768] fp16 transposed
// ============================================================================
__global__ __launch_bounds__(256) void conv_w(const float* __restrict__ W,
                                              __half* __restrict__ Bt, int Nw)
{
    __shared__ float tile[32][33];
    int n0 = blockIdx.x * 32, k0 = blockIdx.y * 32;
    for (int i = threadIdx.y; i < 32; i += 8)
        tile[i][threadIdx.x] = W[(size_t)(k0 + i) * Nw + n0 + threadIdx.x];
    __syncthreads();
    for (int i = threadIdx.y; i < 32; i += 8) {
        int n = n0 + i, k = k0 + threadIdx.x;
        Bt[(size_t)n * Cdim + k] = __float2half(tile[threadIdx.x][i]);
    }
}

// ============================================================================
// HMMA fp16 GEMM: D[128x128] = A[128x768] * B[128x768]^T, 24 steps of BK=32
// 256 threads = 8 warps (2x4), warp tile 64x32. Double-buffered cp.async.
// EPI 0: scatter into g_qkv with QK scale.  EPI 1: +bias -> out.
// ============================================================================
#define SROW 40                        // smem row stride in fp16 (80B, conflict-free)
#define MATB (128 * SROW * 2)          // bytes per 128x32 matrix = 10240
#define STAGE_BYTES (2 * MATB)         // A + B = 20480
#define GEMM_SMEM (2 * STAGE_BYTES)    // 40960

template<int EPI>
__global__ __launch_bounds__(256)
void hmma_gemm(const float* __restrict__ bias, float* __restrict__ out)
{
    extern __shared__ __align__(16) char dsm[];
    const uint32_t smem0 = smem_u32(dsm);

    const int tid = threadIdx.x;
    const int warp = tid >> 5, lane = tid & 31;
    const int wm = warp & 1, wn = warp >> 1;   // 2 x 4 warp grid

    const __half* Ag = (EPI == 0) ? g_Ah : g_Xh;
    const __half* Bg = (EPI == 0) ? g_Bq : g_Bp;

    // loader mapping: row = tid>>1, 16 elements at (tid&1)*16 (2 x 16B chunks)
    const int lrow = tid >> 1;
    const int lcolE = (tid & 1) * 16;
    const __half* Agp = Ag + (size_t)(blockIdx.y * 128 + lrow) * Cdim + lcolE;
    const __half* Bgp = Bg + (size_t)(blockIdx.x * 128 + lrow) * Cdim + lcolE;
    const uint32_t st_off = ((uint32_t)lrow * SROW + lcolE) * 2;

    float acc[4][4][4];
#pragma unroll
    for (int i = 0; i < 4; i++)
#pragma unroll
        for (int j = 0; j < 4; j++)
#pragma unroll
            for (int k = 0; k < 4; k++) acc[i][j][k] = 0.f;

    // ldmatrix per-thread offsets (within one MATB matrix)
    const int l15 = lane & 15;
    const uint32_t a_off = ((uint32_t)(wm * 64 + l15) * SROW + (lane >> 4) * 8) * 2;
    const uint32_t b_off = ((uint32_t)(wn * 32 + ((lane >> 4) & 1) * 8 + (lane & 7)) * SROW
                           + ((lane >> 3) & 1) * 8) * 2;

    const int NIT = 24;   // k = it*32

    // prologue: stage 0  (A at +0, B at +MATB)
    {
        const uint32_t sa = smem0;
        CP16(sa + st_off,              Agp + 0);
        CP16(sa + st_off + 16,         Agp + 8);
        CP16(sa + MATB + st_off,       Bgp + 0);
        CP16(sa + MATB + st_off + 16,  Bgp + 8);
        CP_COMMIT();
    }

    for (int it = 0; it < NIT; ++it) {
        CP_WAIT0();           // stage `it` resident
        __syncthreads();      // all warps done with the other buffer

        if (it + 1 < NIT) {   // refill other buffer with stage it+1
            const uint32_t sa = smem0 + ((it + 1) & 1) * STAGE_BYTES;
            const int k0 = (it + 1) * 32;
            CP16(sa + st_off,              Agp + k0);
            CP16(sa + st_off + 16,         Agp + k0 + 8);
            CP16(sa + MATB + st_off,       Bgp + k0);
            CP16(sa + MATB + st_off + 16,  Bgp + k0 + 8);
        }
        CP_COMMIT();          // empty commits keep group count semantics

        const uint32_t abase = smem0 + (it & 1) * STAGE_BYTES;
        const uint32_t bbase = abase + MATB;

#pragma unroll
        for (int ks = 0; ks < 2; ks++) {
            const uint32_t kso = (uint32_t)(ks * 16) * 2;
            uint32_t b[4][2];
#pragma unroll
            for (int nb = 0; nb < 2; nb++)
                ldsm_x4(b[2 * nb][0], b[2 * nb][1], b[2 * nb + 1][0], b[2 * nb + 1][1],
                        bbase + b_off + (uint32_t)(nb * 16 * SROW) * 2 + kso);
#pragma unroll
            for (int ma = 0; ma < 4; ma++) {
                uint32_t a[4];
                ldsm_x4(a[0], a[1], a[2], a[3],
                        abase + a_off + (uint32_t)(ma * 16 * SROW) * 2 + kso);
#pragma unroll
                for (int na = 0; na < 4; na++) mma16816(acc[ma][na], a, b[na]);
            }
        }
    }

    // ---------------- epilogue ----------------
#pragma unroll
    for (int ma = 0; ma < 4; ma++) {
        const int r0 = blockIdx.y * 128 + wm * 64 + ma * 16 + (lane >> 2);
#pragma unroll
        for (int na = 0; na < 4; na++) {
            const int c = blockIdx.x * 128 + wn * 32 + na * 8 + (lane & 3) * 2;
            if (EPI == 0) {
                const int which = c / 768;
                const int rem = c - which * 768;
                const int h = rem >> 6;
                const int dd = rem & 63;
                const float sc = (which < 2) ? QK_SCALE : 1.0f;
#pragma unroll
                for (int half = 0; half < 2; half++) {
                    const int r = r0 + half * 8;
                    const int b = r >> 11;
                    const int n = r & 2047;
                    float2 v;
                    v.x = acc[ma][na][2 * half + 0] * sc;
                    v.y = acc[ma][na][2 * half + 1] * sc;
                    *(float2*)(g_qkv + (((size_t)which * BH + b * Hn + h) * Nseq + n) * Dh + dd) = v;
                }
            } else {
                const float bx_ = bias[c], by_ = bias[c + 1];
#pragma unroll
                for (int half = 0; half < 2; half++) {
                    const int r = r0 + half * 8;
                    float2 v;
                    v.x = acc[ma][na][2 * half + 0] + bx_;
                    v.y = acc[ma][na][2 * half + 1] + by_;
                    *(float2*)(out + (size_t)r * Cdim + c) = v;
                }
            }
        }
    }
}

// ============================================================================
// Landmark pooling: mean over contiguous chunks of 64
// ============================================================================
__global__ void pool_kernel()
{
    int idx = blockIdx.x * 256 + threadIdx.x;
    int dd = idx & 63;
    int i = (idx >> 6) & 31;
    int rest = idx >> 11;            // which*96 + bh  (which in {0,1})
    const float* src = g_qkv + (size_t)rest * Nseq * Dh + (size_t)(i * 64) * Dh + dd;
    float s = 0.f;
#pragma unroll 8
    for (int t = 0; t < 64; t++) s += src[(size_t)t * Dh];
    g_lm[idx] = s * (1.0f / 64.0f);
}

// ============================================================================
// kernel_2 = softmax(Q_l K_l^T) + Newton-Schulz pseudo-inverse (6 iters)
// ============================================================================
__global__ __launch_bounds__(1024)
void newton_kernel()
{
    int bh = blockIdx.x;
    int j = threadIdx.x, i = threadIdx.y;
    __shared__ float Ql[32][65], Kl[32][65];
    __shared__ float Km[32][33], Vm[32][33], KV[32][33], Tm[32][33];
    __shared__ float red[1];

    int t = i * 32 + j;
    for (int e = t; e < Mlm * Dh; e += 1024) {
        Ql[e >> 6][e & 63] = g_lm[(size_t)bh * (Mlm * Dh) + e];
        Kl[e >> 6][e & 63] = g_lm[(size_t)(BH + bh) * (Mlm * Dh) + e];
    }
    __syncthreads();

    float s = 0.f;
#pragma unroll
    for (int dd = 0; dd < 64; dd++) s += Ql[i][dd] * Kl[j][dd];
    float mx = s;
    for (int o = 16; o; o >>= 1) mx = fmaxf(mx, __shfl_xor_sync(~0u, mx, o));
    float p = expf(s - mx);
    float sm = p;
    for (int o = 16; o; o >>= 1) sm += __shfl_xor_sync(~0u, sm, o);
    p /= sm;
    Km[i][j] = p;
    __syncthreads();

    if (i == 0) {
        float cs = 0.f;
        for (int r = 0; r < 32; r++) cs += Km[r][j];
        float m2 = cs;
        for (int o = 16; o; o >>= 1) m2 = fmaxf(m2, __shfl_xor_sync(~0u, m2, o));
        if (j == 0) red[0] = m2;
    }
    __syncthreads();
    float denom = red[0];
    Vm[i][j] = Km[j][i] / denom;
    __syncthreads();

    for (int it = 0; it < 6; it++) {
        float kv = 0.f;
#pragma unroll
        for (int k = 0; k < 32; k++) kv += Km[i][k] * Vm[k][j];
        KV[i][j] = kv;
        __syncthreads();
        Tm[i][j] = (i == j ? 7.0f : 0.0f) - kv;
        __syncthreads();
        float u = 0.f;
#pragma unroll
        for (int k = 0; k < 32; k++) u += KV[i][k] * Tm[k][j];
        __syncthreads();
        Tm[i][j] = (i == j ? 15.0f : 0.0f) - u;
        __syncthreads();
        u = 0.f;
#pragma unroll
        for (int k = 0; k < 32; k++) u += KV[i][k] * Tm[k][j];
        __syncthreads();
        Tm[i][j] = (i == j ? 13.0f : 0.0f) - u;
        __syncthreads();
        u = 0.f;
#pragma unroll
        for (int k = 0; k < 32; k++) u += Vm[i][k] * Tm[k][j];
        u *= 0.25f;
        __syncthreads();
        Vm[i][j] = u;
        __syncthreads();
    }
    g_inv[((size_t)bh * 32 + i) * 32 + j] = Vm[i][j];
}

// ============================================================================
// flash_k3_part: partial softmax(Q_l K^T) @ V over a 256-token chunk
// grid (96, 8), 512 threads: 16 warps x 2 landmark rows. 64-token tiles.
// ============================================================================
__global__ __launch_bounds__(512)
void flash_k3_part()
{
    int bh = blockIdx.x;
    int chunk = blockIdx.y;
    int tid = threadIdx.x;
    int w = tid >> 5, l = tid & 31;
    __shared__ float Ql[32][65];
    __shared__ float Ks[64][65], Vs[64][65];
    __shared__ float Ps[32][65];

    const float* Kg = g_qkv + ((size_t)1 * BH + bh) * Nseq * Dh;
    const float* Vg = g_qkv + ((size_t)2 * BH + bh) * Nseq * Dh;

    for (int e = tid; e < Mlm * Dh; e += 512)
        Ql[e >> 6][e & 63] = g_lm[(size_t)bh * (Mlm * Dh) + e];

    const int r0 = w * 2, r1 = r0 + 1;
    float m0 = -1e30f, l0 = 0.f, o00 = 0.f, o01 = 0.f;
    float m1 = -1e30f, l1 = 0.f, o10 = 0.f, o11 = 0.f;

    const int tbeg = chunk * 256;
    for (int t0 = tbeg; t0 < tbeg + 256; t0 += 64) {
        __syncthreads();
        for (int e = tid; e < 64 * Dh; e += 512) {
            int rr = e >> 6, c = e & 63;
            Ks[rr][c] = Kg[(size_t)(t0 + rr) * Dh + c];
            Vs[rr][c] = Vg[(size_t)(t0 + rr) * Dh + c];
        }
        __syncthreads();
        // ---- row r0 ----
        {
            float sA = 0.f, sB = 0.f;
#pragma unroll
            for (int dd = 0; dd < 64; dd++) {
                float q = Ql[r0][dd];
                sA += q * Ks[l][dd];
                sB += q * Ks[l + 32][dd];
            }
            float tm = fmaxf(sA, sB);
            for (int o = 16; o; o >>= 1) tm = fmaxf(tm, __shfl_xor_sync(~0u, tm, o));
            float nm = fmaxf(m0, tm);
            float alpha = expf(m0 - nm);
            float pA = expf(sA - nm), pB = expf(sB - nm);
            float ps = pA + pB;
            for (int o = 16; o; o >>= 1) ps += __shfl_xor_sync(~0u, ps, o);
            l0 = l0 * alpha + ps;
            o00 *= alpha; o01 *= alpha;
            Ps[r0][l] = pA; Ps[r0][l + 32] = pB;
            __syncwarp();
#pragma unroll
            for (int k = 0; k < 64; k++) {
                float pk = Ps[r0][k];
                o00 += pk * Vs[k][2 * l];
                o01 += pk * Vs[k][2 * l + 1];
            }
            m0 = nm;
        }
        // ---- row r1 ----
        {
            float sA = 0.f, sB = 0.f;
#pragma unroll
            for (int dd = 0; dd < 64; dd++) {
                float q = Ql[r1][dd];
                sA += q * Ks[l][dd];
                sB += q * Ks[l + 32][dd];
            }
            float tm = fmaxf(sA, sB);
            for (int o = 16; o; o >>= 1) tm = fmaxf(tm, __shfl_xor_sync(~0u, tm, o));
            float nm = fmaxf(m1, tm);
            float alpha = expf(m1 - nm);
            float pA = expf(sA - nm), pB = expf(sB - nm);
            float ps = pA + pB;
            for (int o = 16; o; o >>= 1) ps += __shfl_xor_sync(~0u, ps, o);
            l1 = l1 * alpha + ps;
            o10 *= alpha; o11 *= alpha;
            Ps[r1][l] = pA; Ps[r1][l + 32] = pB;
            __syncwarp();
#pragma unroll
            for (int k = 0; k < 64; k++) {
                float pk = Ps[r1][k];
                o10 += pk * Vs[k][2 * l];
                o11 += pk * Vs[k][2 * l + 1];
            }
            m1 = nm;
        }
    }
    float* P0 = g_Fpart + (((size_t)bh * 8 + chunk) * Mlm + r0) * 66;
    float* P1 = g_Fpart + (((size_t)bh * 8 + chunk) * Mlm + r1) * 66;
    P0[2 * l] = o00; P0[2 * l + 1] = o01;
    P1[2 * l] = o10; P1[2 * l + 1] = o11;
    if (l == 0) { P0[64] = m0; P0[65] = l0; P1[64] = m1; P1[65] = l1; }
}

// combine 8 partials -> g_F  (grid 96, block (64,8))
__global__ __launch_bounds__(512)
void flash_combine()
{
    int bh = blockIdx.x;
    int d = threadIdx.x;
    for (int r = threadIdx.y; r < Mlm; r += 8) {
        const float* base = g_Fpart + (((size_t)bh * 8) * Mlm + r) * 66;
        float mstar = -1e30f;
#pragma unroll
        for (int c = 0; c < 8; c++) mstar = fmaxf(mstar, base[(size_t)c * Mlm * 66 + 64]);
        float L = 0.f, acc = 0.f;
#pragma unroll
        for (int c = 0; c < 8; c++) {
            const float* pc = base + (size_t)c * Mlm * 66;
            float e = expf(pc[64] - mstar);
            L += pc[65] * e;
            acc += pc[d] * e;
        }
        g_F[((size_t)bh * Mlm + r) * Dh + d] = acc / L;
    }
}

// ============================================================================
// X = softmax(Q K_l^T) @ (inv @ F)  -> writes fp16 rows of g_Xh
// ============================================================================
__global__ __launch_bounds__(128)
void nys_out()
{
    int bh = blockIdx.y;
    int b = bh / Hn, h = bh - b * Hn;
    int chunk = blockIdx.x;
    int tid = threadIdx.x;

    __shared__ float Kl[32][65];
    __shared__ float Fs[32][65];
    __shared__ float Gs[32][65];
    __shared__ float invs[32][33];

    for (int e = tid; e < Mlm * Dh; e += 128) {
        Kl[e >> 6][e & 63] = g_lm[(size_t)(BH + bh) * (Mlm * Dh) + e];
        Fs[e >> 6][e & 63] = g_F[(size_t)bh * (Mlm * Dh) + e];
    }
    for (int e = tid; e < Mlm * Mlm; e += 128)
        invs[e >> 5][e & 31] = g_inv[(size_t)bh * (Mlm * Mlm) + e];
    __syncthreads();

    for (int e = tid; e < Mlm * Dh; e += 128) {
        int r = e >> 6, c = e & 63;
        float s = 0.f;
#pragma unroll
        for (int k = 0; k < 32; k++) s += invs[r][k] * Fs[k][c];
        Gs[r][c] = s;
    }
    __syncthreads();

    int n = chunk * 128 + tid;
    const float* Qg = g_qkv + ((size_t)bh * Nseq + n) * Dh;
    float q[64];
#pragma unroll
    for (int e = 0; e < 16; e++)
        *(float4*)&q[4 * e] = *(const float4*)&Qg[4 * e];

    float logits[32];
#pragma unroll
    for (int j = 0; j < 32; j++) {
        float s = 0.f;
#pragma unroll
        for (int dd = 0; dd < 64; dd++) s += q[dd] * Kl[j][dd];
        logits[j] = s;
    }
    float mx = -1e30f;
#pragma unroll
    for (int j = 0; j < 32; j++) mx = fmaxf(mx, logits[j]);
    float sum = 0.f;
#pragma unroll
    for (int j = 0; j < 32; j++) { logits[j] = expf(logits[j] - mx); sum += logits[j]; }
    float is = 1.f / sum;
#pragma unroll
    for (int j = 0; j < 32; j++) logits[j] *= is;

    // output row in g_Xh: r = b*2048 + n, cols h*64 + dd
    __half* row = g_Xh + ((size_t)b * Nseq + n) * Cdim + h * Dh;
#pragma unroll
    for (int d4 = 0; d4 < 16; d4++) {
        float o[4] = {0.f, 0.f, 0.f, 0.f};
#pragma unroll
        for (int j = 0; j < 32; j++) {
            float pj = logits[j];
            o[0] += pj * Gs[j][4 * d4 + 0];
            o[1] += pj * Gs[j][4 * d4 + 1];
            o[2] += pj * Gs[j][4 * d4 + 2];
            o[3] += pj * Gs[j][4 * d4 + 3];
        }
        __half2 h0 = {__float2half(o[0]), __float2half(o[1])};
        __half2 h1 = {__float2half(o[2]), __float2half(o[3])};
        int c = 4 * d4;
        *(__half2*)(row + c) = h0;
        *(__half2*)(row + c + 2) = h1;
    }
}

// ============================================================================
extern "C" void kernel_launch(void* const* d_in, const int* in_sizes, int n_in,
                              void* d_out, int out_size)
{
    const float* x      = (const float*)d_in[0];  // [8,2048,768]
    const float* w_qkv  = (const float*)d_in[1];  // [768,2304]
    const float* w_proj = (const float*)d_in[2];  // [768,768]
    const float* b_proj = (const float*)d_in[3];  // [768]
    float* out = (float*)d_out;                   // [8,2048,768]

    __half *gBq, *gBp;
    cudaGetSymbolAddress((void**)&gBq, g_Bq);
    cudaGetSymbolAddress((void**)&gBp, g_Bp);

    static int attr_done = 0;
    if (!attr_done) {
        cudaFuncSetAttribute(hmma_gemm<0>, cudaFuncAttributeMaxDynamicSharedMemorySize, GEMM_SMEM);
        cudaFuncSetAttribute(hmma_gemm<1>, cudaFuncAttributeMaxDynamicSharedMemorySize, GEMM_SMEM);
        attr_done = 1;
    }

    // 1. fp16 conversions
    conv_a<<<16384 * 192 / 256, 256>>>(x);
    conv_w<<<dim3(2304 / 32, Cdim / 32), dim3(32, 8)>>>(w_qkv, gBq, 2304);
    conv_w<<<dim3(Cdim / 32, Cdim / 32), dim3(32, 8)>>>(w_proj, gBp, Cdim);
    // 2. qkv GEMM on HMMA fp16 (M=16384, N=2304, K=768) -> g_qkv (scaled)
    hmma_gemm<0><<<dim3(2304 / 128, 16384 / 128), 256, GEMM_SMEM>>>(nullptr, nullptr);
    // 3. landmark pooling
    pool_kernel<<<2 * BH * Mlm * Dh / 256, 256>>>();
    // 4. kernel_2 + Newton-Schulz inverse
    newton_kernel<<<BH, dim3(32, 32)>>>();
    // 5. F = softmax(Q_l K^T) @ V  (split over 8 chunks + combine)
    flash_k3_part<<<dim3(BH, 8), 512>>>();
    flash_combine<<<BH, dim3(64, 8)>>>();
    // 6. X = softmax(Q K_l^T) @ (inv @ F) -> g_Xh (fp16)
    nys_out<<<dim3(Nseq / 128, BH), 128>>>();
    // 7. proj GEMM on HMMA fp16 (M=16384, N=768, K=768) + bias -> out
    hmma_gemm<1><<<dim3(Cdim / 128, 16384 / 128), 256, GEMM_SMEM>>>(b_proj, out);
}

// round 16
// speedup vs baseline: 2.0553x; 1.2372x over previous
#include <cuda_runtime.h>
#include <cuda_bf16.h>
#include <cuda_fp16.h>
#include <math.h>
#include <stdint.h>

// Problem constants
#define Bsz 8
#define Nseq 2048
#define Cdim 768
#define Hn 12
#define Dh 64
#define Mlm 32
#define BH (Bsz*Hn)            // 96
#define QK_SCALE 0.35355339059327373f  // 64^-0.25

// ---------------- scratch (device globals; no runtime alloc allowed) -------
__device__ float g_qkv[(size_t)3 * BH * Nseq * Dh];         // [3][96][2048][64]
__device__ float g_lm[(size_t)2 * BH * Mlm * Dh];           // Q_l then K_l
__device__ float g_inv[(size_t)BH * Mlm * Mlm];             // pinv(kernel_2)
__device__ float g_F[(size_t)BH * Mlm * Dh];                // kernel_3 @ V
__device__ float g_Fpart[(size_t)BH * 8 * Mlm * 66];        // partial flash outputs
__device__ __half g_Ah[(size_t)16384 * Cdim];               // fp16 of x
__device__ __half g_Xh[(size_t)16384 * Cdim];               // fp16 of attention out
__device__ __half g_Bq[(size_t)2304 * Cdim];                // w_qkv^T fp16 [2304][768]
__device__ __half g_Bp[(size_t)Cdim * Cdim];                // w_proj^T fp16 [768][768]

// ============================================================================
// PTX helpers (baseline ISA only: cp.async / ldmatrix / mma.sync)
// ============================================================================
__device__ __forceinline__ uint32_t smem_u32(const void* p) {
    uint32_t a;
    asm("{ .reg .u64 t; cvta.to.shared.u64 t, %1; cvt.u32.u64 %0, t; }" : "=r"(a) : "l"(p));
    return a;
}
#define CP16(dst, src) \
    asm volatile("cp.async.cg.shared.global [%0], [%1], 16;" :: "r"(dst), "l"(src))
#define CP_COMMIT() asm volatile("cp.async.commit_group;" ::: "memory")
#define CP_WAIT0()  asm volatile("cp.async.wait_group 0;" ::: "memory")

__device__ __forceinline__ void ldsm_x4(uint32_t& r0, uint32_t& r1, uint32_t& r2, uint32_t& r3, uint32_t addr) {
    asm volatile("ldmatrix.sync.aligned.m8n8.x4.shared.b16 {%0,%1,%2,%3}, [%4];"
                 : "=r"(r0), "=r"(r1), "=r"(r2), "=r"(r3) : "r"(addr));
}
__device__ __forceinline__ void mma16816(float* d, const uint32_t* a, const uint32_t* b) {
    asm("mma.sync.aligned.m16n8k16.row.col.f32.f16.f16.f32 "
        "{%0,%1,%2,%3}, {%4,%5,%6,%7}, {%8,%9}, {%0,%1,%2,%3};"
        : "+f"(d[0]), "+f"(d[1]), "+f"(d[2]), "+f"(d[3])
        : "r"(a[0]), "r"(a[1]), "r"(a[2]), "r"(a[3]), "r"(b[0]), "r"(b[1]));
}

// ============================================================================
// conv_a: x [16384][768] f32 -> g_Ah [16384][768] fp16
// ============================================================================
__global__ __launch_bounds__(256) void conv_a(const float* __restrict__ X)
{
    int idx = blockIdx.x * 256 + threadIdx.x;   // 16384*192 total
    int r = idx / 192, c = (idx - r * 192) * 4;
    float4 v = *(const float4*)(X + (size_t)r * Cdim + c);
    __half2 h0 = {__float2half(v.x), __float2half(v.y)};
    __half2 h1 = {__float2half(v.z), __float2half(v.w)};
    __half* row = g_Ah + (size_t)r * Cdim;
    *(__half2*)(row + c) = h0;
    *(__half2*)(row + c + 2) = h1;
}

// ============================================================================
// conv_w: W [768][Nw] f32 -> Bt [Nw][768] fp16 transposed
// ============================================================================
__global__ __launch_bounds__(256) void conv_w(const float* __restrict__ W,
                                              __half* __restrict__ Bt, int Nw)
{
    __shared__ float tile[32][33];
    int n0 = blockIdx.x * 32, k0 = blockIdx.y * 32;
    for (int i = threadIdx.y; i < 32; i += 8)
        tile[i][threadIdx.x] = W[(size_t)(k0 + i) * Nw + n0 + threadIdx.x];
    __syncthreads();
    for (int i = threadIdx.y; i < 32; i += 8) {
        int n = n0 + i, k = k0 + threadIdx.x;
        Bt[(size_t)n * Cdim + k] = __float2half(tile[threadIdx.x][i]);
    }
}

// ============================================================================
// HMMA fp16 GEMM: D[128x128] = A[128x768] * B[128x768]^T, 24 steps of BK=32
// 256 threads = 8 warps (2x4), warp tile 64x32. Double-buffered cp.async.
// EPI 0: scatter into g_qkv with QK scale.  EPI 1: +bias -> out.
// ============================================================================
#define SROW 40                        // smem row stride in fp16 (80B, conflict-free)
#define MATB (128 * SROW * 2)          // bytes per 128x32 matrix = 10240
#define STAGE_BYTES (2 * MATB)         // A + B = 20480
#define GEMM_SMEM (2 * STAGE_BYTES)    // 40960

template<int EPI>
__global__ __launch_bounds__(256)
void hmma_gemm(const float* __restrict__ bias, float* __restrict__ out)
{
    extern __shared__ __align__(16) char dsm[];
    const uint32_t smem0 = smem_u32(dsm);

    const int tid = threadIdx.x;
    const int warp = tid >> 5, lane = tid & 31;
    const int wm = warp & 1, wn = warp >> 1;   // 2 x 4 warp grid

    const __half* Ag = (EPI == 0) ? g_Ah : g_Xh;
    const __half* Bg = (EPI == 0) ? g_Bq : g_Bp;

    // loader mapping: row = tid>>1, 16 elements at (tid&1)*16 (2 x 16B chunks)
    const int lrow = tid >> 1;
    const int lcolE = (tid & 1) * 16;
    const __half* Agp = Ag + (size_t)(blockIdx.y * 128 + lrow) * Cdim + lcolE;
    const __half* Bgp = Bg + (size_t)(blockIdx.x * 128 + lrow) * Cdim + lcolE;
    const uint32_t st_off = ((uint32_t)lrow * SROW + lcolE) * 2;

    float acc[4][4][4];
#pragma unroll
    for (int i = 0; i < 4; i++)
#pragma unroll
        for (int j = 0; j < 4; j++)
#pragma unroll
            for (int k = 0; k < 4; k++) acc[i][j][k] = 0.f;

    // ldmatrix per-thread offsets (within one MATB matrix)
    const int l15 = lane & 15;
    const uint32_t a_off = ((uint32_t)(wm * 64 + l15) * SROW + (lane >> 4) * 8) * 2;
    const uint32_t b_off = ((uint32_t)(wn * 32 + ((lane >> 4) & 1) * 8 + (lane & 7)) * SROW
                           + ((lane >> 3) & 1) * 8) * 2;

    const int NIT = 24;   // k = it*32

    // prologue: stage 0  (A at +0, B at +MATB)
    {
        const uint32_t sa = smem0;
        CP16(sa + st_off,              Agp + 0);
        CP16(sa + st_off + 16,         Agp + 8);
        CP16(sa + MATB + st_off,       Bgp + 0);
        CP16(sa + MATB + st_off + 16,  Bgp + 8);
        CP_COMMIT();
    }

    for (int it = 0; it < NIT; ++it) {
        CP_WAIT0();           // stage `it` resident
        __syncthreads();      // all warps done with the other buffer

        if (it + 1 < NIT) {   // refill other buffer with stage it+1
            const uint32_t sa = smem0 + ((it + 1) & 1) * STAGE_BYTES;
            const int k0 = (it + 1) * 32;
            CP16(sa + st_off,              Agp + k0);
            CP16(sa + st_off + 16,         Agp + k0 + 8);
            CP16(sa + MATB + st_off,       Bgp + k0);
            CP16(sa + MATB + st_off + 16,  Bgp + k0 + 8);
        }
        CP_COMMIT();          // empty commits keep group count semantics

        const uint32_t abase = smem0 + (it & 1) * STAGE_BYTES;
        const uint32_t bbase = abase + MATB;

#pragma unroll
        for (int ks = 0; ks < 2; ks++) {
            const uint32_t kso = (uint32_t)(ks * 16) * 2;
            uint32_t b[4][2];
#pragma unroll
            for (int nb = 0; nb < 2; nb++)
                ldsm_x4(b[2 * nb][0], b[2 * nb][1], b[2 * nb + 1][0], b[2 * nb + 1][1],
                        bbase + b_off + (uint32_t)(nb * 16 * SROW) * 2 + kso);
#pragma unroll
            for (int ma = 0; ma < 4; ma++) {
                uint32_t a[4];
                ldsm_x4(a[0], a[1], a[2], a[3],
                        abase + a_off + (uint32_t)(ma * 16 * SROW) * 2 + kso);
#pragma unroll
                for (int na = 0; na < 4; na++) mma16816(acc[ma][na], a, b[na]);
            }
        }
    }

    // ---------------- epilogue ----------------
#pragma unroll
    for (int ma = 0; ma < 4; ma++) {
        const int r0 = blockIdx.y * 128 + wm * 64 + ma * 16 + (lane >> 2);
#pragma unroll
        for (int na = 0; na < 4; na++) {
            const int c = blockIdx.x * 128 + wn * 32 + na * 8 + (lane & 3) * 2;
            if (EPI == 0) {
                const int which = c / 768;
                const int rem = c - which * 768;
                const int h = rem >> 6;
                const int dd = rem & 63;
                const float sc = (which < 2) ? QK_SCALE : 1.0f;
#pragma unroll
                for (int half = 0; half < 2; half++) {
                    const int r = r0 + half * 8;
                    const int b = r >> 11;
                    const int n = r & 2047;
                    float2 v;
                    v.x = acc[ma][na][2 * half + 0] * sc;
                    v.y = acc[ma][na][2 * half + 1] * sc;
                    *(float2*)(g_qkv + (((size_t)which * BH + b * Hn + h) * Nseq + n) * Dh + dd) = v;
                }
            } else {
                const float bx_ = bias[c], by_ = bias[c + 1];
#pragma unroll
                for (int half = 0; half < 2; half++) {
                    const int r = r0 + half * 8;
                    float2 v;
                    v.x = acc[ma][na][2 * half + 0] + bx_;
                    v.y = acc[ma][na][2 * half + 1] + by_;
                    *(float2*)(out + (size_t)r * Cdim + c) = v;
                }
            }
        }
    }
}

// ============================================================================
// Landmark pooling: mean over contiguous chunks of 64 (float4 per thread)
// ============================================================================
__global__ void pool_kernel()
{
    int idx = blockIdx.x * 256 + threadIdx.x;   // 98304 total
    int dd = (idx & 15) * 4;
    int i = (idx >> 4) & 31;
    int rest = idx >> 9;            // which*96 + bh  (which in {0,1})
    const float* src = g_qkv + (size_t)rest * Nseq * Dh + (size_t)(i * 64) * Dh + dd;
    float4 s = make_float4(0.f, 0.f, 0.f, 0.f);
#pragma unroll 8
    for (int t = 0; t < 64; t++) {
        float4 v = *(const float4*)(src + (size_t)t * Dh);
        s.x += v.x; s.y += v.y; s.z += v.z; s.w += v.w;
    }
    s.x *= (1.0f / 64.0f); s.y *= (1.0f / 64.0f);
    s.z *= (1.0f / 64.0f); s.w *= (1.0f / 64.0f);
    *(float4*)(g_lm + (size_t)rest * (Mlm * Dh) + i * Dh + dd) = s;
}

// ============================================================================
// kernel_2 = softmax(Q_l K_l^T) + Newton-Schulz pseudo-inverse (6 iters)
// ============================================================================
__global__ __launch_bounds__(1024)
void newton_kernel()
{
    int bh = blockIdx.x;
    int j = threadIdx.x, i = threadIdx.y;
    __shared__ float Ql[32][65], Kl[32][65];
    __shared__ float Km[32][33], Vm[32][33], KV[32][33], Tm[32][33];
    __shared__ float red[1];

    int t = i * 32 + j;
    for (int e = t; e < Mlm * Dh; e += 1024) {
        Ql[e >> 6][e & 63] = g_lm[(size_t)bh * (Mlm * Dh) + e];
        Kl[e >> 6][e & 63] = g_lm[(size_t)(BH + bh) * (Mlm * Dh) + e];
    }
    __syncthreads();

    float s = 0.f;
#pragma unroll
    for (int dd = 0; dd < 64; dd++) s += Ql[i][dd] * Kl[j][dd];
    float mx = s;
    for (int o = 16; o; o >>= 1) mx = fmaxf(mx, __shfl_xor_sync(~0u, mx, o));
    float p = expf(s - mx);
    float sm = p;
    for (int o = 16; o; o >>= 1) sm += __shfl_xor_sync(~0u, sm, o);
    p /= sm;
    Km[i][j] = p;
    __syncthreads();

    if (i == 0) {
        float cs = 0.f;
        for (int r = 0; r < 32; r++) cs += Km[r][j];
        float m2 = cs;
        for (int o = 16; o; o >>= 1) m2 = fmaxf(m2, __shfl_xor_sync(~0u, m2, o));
        if (j == 0) red[0] = m2;
    }
    __syncthreads();
    float denom = red[0];
    Vm[i][j] = Km[j][i] / denom;
    __syncthreads();

    for (int it = 0; it < 6; it++) {
        float kv = 0.f;
#pragma unroll
        for (int k = 0; k < 32; k++) kv += Km[i][k] * Vm[k][j];
        KV[i][j] = kv;
        __syncthreads();
        Tm[i][j] = (i == j ? 7.0f : 0.0f) - kv;
        __syncthreads();
        float u = 0.f;
#pragma unroll
        for (int k = 0; k < 32; k++) u += KV[i][k] * Tm[k][j];
        __syncthreads();
        Tm[i][j] = (i == j ? 15.0f : 0.0f) - u;
        __syncthreads();
        u = 0.f;
#pragma unroll
        for (int k = 0; k < 32; k++) u += KV[i][k] * Tm[k][j];
        __syncthreads();
        Tm[i][j] = (i == j ? 13.0f : 0.0f) - u;
        __syncthreads();
        u = 0.f;
#pragma unroll
        for (int k = 0; k < 32; k++) u += Vm[i][k] * Tm[k][j];
        u *= 0.25f;
        __syncthreads();
        Vm[i][j] = u;
        __syncthreads();
    }
    g_inv[((size_t)bh * 32 + i) * 32 + j] = Vm[i][j];
}

// ============================================================================
// flash_k3_part: partial softmax(Q_l K^T) @ V over a 256-token chunk
// grid (96, 8), 512 threads: 16 warps x 2 landmark rows. 64-token tiles.
// Fused row pairs + float4 smem loads (rows padded to 68 floats, 16B aligned).
// ============================================================================
__global__ __launch_bounds__(512)
void flash_k3_part()
{
    int bh = blockIdx.x;
    int chunk = blockIdx.y;
    int tid = threadIdx.x;
    int w = tid >> 5, l = tid & 31;
    __shared__ __align__(16) float Ql[32][68];
    __shared__ __align__(16) float Ks[64][68], Vs[64][68];
    __shared__ float Ps[32][68];

    const float* Kg = g_qkv + ((size_t)1 * BH + bh) * Nseq * Dh;
    const float* Vg = g_qkv + ((size_t)2 * BH + bh) * Nseq * Dh;

    for (int e = tid; e < Mlm * 16; e += 512) {
        int rr = e >> 4, c = (e & 15) * 4;
        *(float4*)&Ql[rr][c] = *(const float4*)&g_lm[(size_t)bh * (Mlm * Dh) + rr * Dh + c];
    }

    const int r0 = w * 2, r1 = r0 + 1;
    float m0 = -1e30f, l0 = 0.f, o00 = 0.f, o01 = 0.f;
    float m1 = -1e30f, l1 = 0.f, o10 = 0.f, o11 = 0.f;

    const int tbeg = chunk * 256;
    for (int t0 = tbeg; t0 < tbeg + 256; t0 += 64) {
        __syncthreads();
        for (int e = tid; e < 64 * 16; e += 512) {
            int rr = e >> 4, c = (e & 15) * 4;
            *(float4*)&Ks[rr][c] = *(const float4*)&Kg[(size_t)(t0 + rr) * Dh + c];
            *(float4*)&Vs[rr][c] = *(const float4*)&Vg[(size_t)(t0 + rr) * Dh + c];
        }
        __syncthreads();

        // ---- fused QK for rows r0, r1, tokens l and l+32 ----
        float sA0 = 0.f, sB0 = 0.f, sA1 = 0.f, sB1 = 0.f;
#pragma unroll
        for (int d4 = 0; d4 < 16; d4++) {
            float4 kA = *(float4*)&Ks[l][d4 * 4];
            float4 kB = *(float4*)&Ks[l + 32][d4 * 4];
            float4 q0 = *(float4*)&Ql[r0][d4 * 4];
            float4 q1 = *(float4*)&Ql[r1][d4 * 4];
            sA0 += q0.x * kA.x + q0.y * kA.y + q0.z * kA.z + q0.w * kA.w;
            sB0 += q0.x * kB.x + q0.y * kB.y + q0.z * kB.z + q0.w * kB.w;
            sA1 += q1.x * kA.x + q1.y * kA.y + q1.z * kA.z + q1.w * kA.w;
            sB1 += q1.x * kB.x + q1.y * kB.y + q1.z * kB.z + q1.w * kB.w;
        }
        // ---- softmax updates ----
        float tm0 = fmaxf(sA0, sB0);
        for (int o = 16; o; o >>= 1) tm0 = fmaxf(tm0, __shfl_xor_sync(~0u, tm0, o));
        float nm0 = fmaxf(m0, tm0);
        float alpha0 = expf(m0 - nm0);
        float pA0 = expf(sA0 - nm0), pB0 = expf(sB0 - nm0);
        float ps0 = pA0 + pB0;
        for (int o = 16; o; o >>= 1) ps0 += __shfl_xor_sync(~0u, ps0, o);
        l0 = l0 * alpha0 + ps0;
        o00 *= alpha0; o01 *= alpha0;
        Ps[r0][l] = pA0; Ps[r0][l + 32] = pB0;
        m0 = nm0;

        float tm1 = fmaxf(sA1, sB1);
        for (int o = 16; o; o >>= 1) tm1 = fmaxf(tm1, __shfl_xor_sync(~0u, tm1, o));
        float nm1 = fmaxf(m1, tm1);
        float alpha1 = expf(m1 - nm1);
        float pA1 = expf(sA1 - nm1), pB1 = expf(sB1 - nm1);
        float ps1 = pA1 + pB1;
        for (int o = 16; o; o >>= 1) ps1 += __shfl_xor_sync(~0u, ps1, o);
        l1 = l1 * alpha1 + ps1;
        o10 *= alpha1; o11 *= alpha1;
        Ps[r1][l] = pA1; Ps[r1][l + 32] = pB1;
        m1 = nm1;
        __syncwarp();

        // ---- fused PV for both rows (shared Vs float2 reads) ----
#pragma unroll
        for (int k = 0; k < 64; k++) {
            float2 v = *(float2*)&Vs[k][2 * l];
            float p0 = Ps[r0][k], p1 = Ps[r1][k];
            o00 += p0 * v.x; o01 += p0 * v.y;
            o10 += p1 * v.x; o11 += p1 * v.y;
        }
    }
    float* P0 = g_Fpart + (((size_t)bh * 8 + chunk) * Mlm + r0) * 66;
    float* P1 = g_Fpart + (((size_t)bh * 8 + chunk) * Mlm + r1) * 66;
    P0[2 * l] = o00; P0[2 * l + 1] = o01;
    P1[2 * l] = o10; P1[2 * l + 1] = o11;
    if (l == 0) { P0[64] = m0; P0[65] = l0; P1[64] = m1; P1[65] = l1; }
}

// combine 8 partials -> g_F  (grid 96, block (64,8))
__global__ __launch_bounds__(512)
void flash_combine()
{
    int bh = blockIdx.x;
    int d = threadIdx.x;
    for (int r = threadIdx.y; r < Mlm; r += 8) {
        const float* base = g_Fpart + (((size_t)bh * 8) * Mlm + r) * 66;
        float mstar = -1e30f;
#pragma unroll
        for (int c = 0; c < 8; c++) mstar = fmaxf(mstar, base[(size_t)c * Mlm * 66 + 64]);
        float L = 0.f, acc = 0.f;
#pragma unroll
        for (int c = 0; c < 8; c++) {
            const float* pc = base + (size_t)c * Mlm * 66;
            float e = expf(pc[64] - mstar);
            L += pc[65] * e;
            acc += pc[d] * e;
        }
        g_F[((size_t)bh * Mlm + r) * Dh + d] = acc / L;
    }
}

// ============================================================================
// X = softmax(Q K_l^T) @ (inv @ F)  -> writes fp16 rows of g_Xh
// float4 broadcast smem loads (rows padded to 68 floats)
// ============================================================================
__global__ __launch_bounds__(128)
void nys_out()
{
    int bh = blockIdx.y;
    int b = bh / Hn, h = bh - b * Hn;
    int chunk = blockIdx.x;
    int tid = threadIdx.x;

    __shared__ __align__(16) float Kl[32][68];
    __shared__ __align__(16) float Fs[32][68];
    __shared__ __align__(16) float Gs[32][68];
    __shared__ float invs[32][33];

    for (int e = tid; e < Mlm * 16; e += 128) {
        int rr = e >> 4, c = (e & 15) * 4;
        *(float4*)&Kl[rr][c] = *(const float4*)&g_lm[(size_t)(BH + bh) * (Mlm * Dh) + rr * Dh + c];
        *(float4*)&Fs[rr][c] = *(const float4*)&g_F[(size_t)bh * (Mlm * Dh) + rr * Dh + c];
    }
    for (int e = tid; e < Mlm * Mlm; e += 128)
        invs[e >> 5][e & 31] = g_inv[(size_t)bh * (Mlm * Mlm) + e];
    __syncthreads();

    for (int e = tid; e < Mlm * Dh; e += 128) {
        int r = e >> 6, c = e & 63;
        float s = 0.f;
#pragma unroll
        for (int k = 0; k < 32; k++) s += invs[r][k] * Fs[k][c];
        Gs[r][c] = s;
    }
    __syncthreads();

    int n = chunk * 128 + tid;
    const float* Qg = g_qkv + ((size_t)bh * Nseq + n) * Dh;
    float q[64];
#pragma unroll
    for (int e = 0; e < 16; e++)
        *(float4*)&q[4 * e] = *(const float4*)&Qg[4 * e];

    float logits[32];
#pragma unroll
    for (int j = 0; j < 32; j++) {
        float s = 0.f;
#pragma unroll
        for (int d4 = 0; d4 < 16; d4++) {
            float4 k4 = *(float4*)&Kl[j][4 * d4];
            s += q[4 * d4 + 0] * k4.x + q[4 * d4 + 1] * k4.y
               + q[4 * d4 + 2] * k4.z + q[4 * d4 + 3] * k4.w;
        }
        logits[j] = s;
    }
    float mx = -1e30f;
#pragma unroll
    for (int j = 0; j < 32; j++) mx = fmaxf(mx, logits[j]);
    float sum = 0.f;
#pragma unroll
    for (int j = 0; j < 32; j++) { logits[j] = expf(logits[j] - mx); sum += logits[j]; }
    float is = 1.f / sum;
#pragma unroll
    for (int j = 0; j < 32; j++) logits[j] *= is;

    // output row in g_Xh: r = b*2048 + n, cols h*64 + dd
    __half* row = g_Xh + ((size_t)b * Nseq + n) * Cdim + h * Dh;
#pragma unroll
    for (int d4 = 0; d4 < 16; d4++) {
        float o[4] = {0.f, 0.f, 0.f, 0.f};
#pragma unroll
        for (int j = 0; j < 32; j++) {
            float pj = logits[j];
            float4 g4 = *(float4*)&Gs[j][4 * d4];
            o[0] += pj * g4.x;
            o[1] += pj * g4.y;
            o[2] += pj * g4.z;
            o[3] += pj * g4.w;
        }
        __half2 h0 = {__float2half(o[0]), __float2half(o[1])};
        __half2 h1 = {__float2half(o[2]), __float2half(o[3])};
        int c = 4 * d4;
        *(__half2*)(row + c) = h0;
        *(__half2*)(row + c + 2) = h1;
    }
}

// ============================================================================
extern "C" void kernel_launch(void* const* d_in, const int* in_sizes, int n_in,
                              void* d_out, int out_size)
{
    const float* x      = (const float*)d_in[0];  // [8,2048,768]
    const float* w_qkv  = (const float*)d_in[1];  // [768,2304]
    const float* w_proj = (const float*)d_in[2];  // [768,768]
    const float* b_proj = (const float*)d_in[3];  // [768]
    float* out = (float*)d_out;                   // [8,2048,768]

    __half *gBq, *gBp;
    cudaGetSymbolAddress((void**)&gBq, g_Bq);
    cudaGetSymbolAddress((void**)&gBp, g_Bp);

    static int attr_done = 0;
    if (!attr_done) {
        cudaFuncSetAttribute(hmma_gemm<0>, cudaFuncAttributeMaxDynamicSharedMemorySize, GEMM_SMEM);
        cudaFuncSetAttribute(hmma_gemm<1>, cudaFuncAttributeMaxDynamicSharedMemorySize, GEMM_SMEM);
        attr_done = 1;
    }

    // 1. fp16 conversions
    conv_a<<<16384 * 192 / 256, 256>>>(x);
    conv_w<<<dim3(2304 / 32, Cdim / 32), dim3(32, 8)>>>(w_qkv, gBq, 2304);
    conv_w<<<dim3(Cdim / 32, Cdim / 32), dim3(32, 8)>>>(w_proj, gBp, Cdim);
    // 2. qkv GEMM on HMMA fp16 (M=16384, N=2304, K=768) -> g_qkv (scaled)
    hmma_gemm<0><<<dim3(2304 / 128, 16384 / 128), 256, GEMM_SMEM>>>(nullptr, nullptr);
    // 3. landmark pooling
    pool_kernel<<<2 * BH * Mlm * 16 / 256, 256>>>();
    // 4. kernel_2 + Newton-Schulz inverse
    newton_kernel<<<BH, dim3(32, 32)>>>();
    // 5. F = softmax(Q_l K^T) @ V  (split over 8 chunks + combine)
    flash_k3_part<<<dim3(BH, 8), 512>>>();
    flash_combine<<<BH, dim3(64, 8)>>>();
    // 6. X = softmax(Q K_l^T) @ (inv @ F) -> g_Xh (fp16)
    nys_out<<<dim3(Nseq / 128, BH), 128>>>();
    // 7. proj GEMM on HMMA fp16 (M=16384, N=768, K=768) + bias -> out
    hmma_gemm<1><<<dim3(Cdim / 128, 16384 / 128), 256, GEMM_SMEM>>>(b_proj, out);
}